// round 9
// baseline (speedup 1.0000x reference)
#include <cuda_runtime.h>
#include <cuda_fp16.h>
#include <math.h>
#include <stdint.h>

// ---------------- problem dims ----------------
#define MDIM 16384          // B*S
#define DDIM 1024           // input dim
#define LDIM 1024           // latent
#define L2DIM 2048          // 2L
#define CN 16               // concepts

// ---------------- scratch (device globals; no allocation) ----------------
__device__ float g_h [(size_t)MDIM * L2DIM];    // encoder pre-LN output
__device__ float g_dd[(size_t)MDIM * LDIM];     // decoder mid pre-LN
__device__ __half g_zch[(size_t)MDIM * LDIM];   // z_causal fp16
__device__ __half g_xh [(size_t)MDIM * DDIM];   // x in fp16
__device__ __half g_zth[(size_t)MDIM * LDIM];   // concept out fp16
__device__ __half g_dh [(size_t)MDIM * LDIM];   // decoder mid fp16
__device__ __half g_ewh[(size_t)L2DIM * DDIM];  // enc_w fp16
__device__ __half g_w1h[(size_t)LDIM * LDIM];   // dec_w1 fp16
__device__ __half g_w2h[(size_t)DDIM * LDIM];   // dec_w2 fp16
__device__ float g_dag[CN * CN];
__device__ double g_kl_sum;
__device__ double g_recon_sum;
__device__ double g_dag_loss;

// ---------------- PTX helpers (baseline ISA only — no tcgen05 on sm_103) ----------
__device__ __forceinline__ uint32_t smem_u32(const void* p) {
    return (uint32_t)__cvta_generic_to_shared(p);
}
__device__ __forceinline__ void cp_async16(uint32_t dst, const void* src) {
    asm volatile("cp.async.cg.shared.global [%0], [%1], 16;" :: "r"(dst), "l"(src));
}
__device__ __forceinline__ void cp_commit() {
    asm volatile("cp.async.commit_group;" ::: "memory");
}
__device__ __forceinline__ void cp_wait1() {
    asm volatile("cp.async.wait_group 1;" ::: "memory");
}
__device__ __forceinline__ void cp_wait0() {
    asm volatile("cp.async.wait_group 0;" ::: "memory");
}
__device__ __forceinline__ void ldm_x4(uint32_t* r, uint32_t addr) {
    asm volatile("ldmatrix.sync.aligned.m8n8.x4.shared.b16 {%0,%1,%2,%3}, [%4];"
                 : "=r"(r[0]), "=r"(r[1]), "=r"(r[2]), "=r"(r[3]) : "r"(addr));
}
__device__ __forceinline__ void mma_fp16(float* c, const uint32_t* a, const uint32_t* b) {
    asm volatile(
        "mma.sync.aligned.m16n8k16.row.col.f32.f16.f16.f32 "
        "{%0,%1,%2,%3}, {%4,%5,%6,%7}, {%8,%9}, {%0,%1,%2,%3};"
        : "+f"(c[0]), "+f"(c[1]), "+f"(c[2]), "+f"(c[3])
        : "r"(a[0]), "r"(a[1]), "r"(a[2]), "r"(a[3]), "r"(b[0]), "r"(b[1]));
}

// ---------------- dag (+ loss-accumulator init) ----------------
// trace(expm(dag)) == C exactly (dag strictly lower triangular -> nilpotent).
__global__ void dag_kernel(const float* __restrict__ dag_w) {
    int tid = threadIdx.x;            // 256 threads
    int i = tid >> 4, j = tid & 15;
    float v = 0.f;
    if (i > j) {
        float x = dag_w[tid];
        v = (x > 20.f) ? x : log1pf(expf(x));
    }
    g_dag[tid] = v;
    __shared__ float sh[8];
    float s = v;
    #pragma unroll
    for (int o = 16; o; o >>= 1) s += __shfl_xor_sync(0xffffffffu, s, o);
    if ((tid & 31) == 0) sh[tid >> 5] = s;
    __syncthreads();
    if (tid == 0) {
        float t = 0.f;
        #pragma unroll
        for (int w = 0; w < 8; w++) t += sh[w];
        g_dag_loss = (double)t + 16.0;
        g_kl_sum = 0.0;
        g_recon_sum = 0.0;
    }
}

// ---------------- fp32 -> fp16 convert, all 4 arrays, 2-way ILP ----------------
// block handles 4096 elems: [0,4096) x | [4096,4608) enc_w | [4608,4864) w1 | [4864,5120) w2
__global__ __launch_bounds__(256)
void conv_all_kernel(const float* __restrict__ X0, __half* __restrict__ H0,
                     const float* __restrict__ X1, __half* __restrict__ H1,
                     const float* __restrict__ X2, __half* __restrict__ H2,
                     const float* __restrict__ X3, __half* __restrict__ H3)
{
    int b = blockIdx.x;
    const float* X; __half* H; int base;
    if (b < 4096)      { X = X0; H = H0; base = b; }
    else if (b < 4608) { X = X1; H = H1; base = b - 4096; }
    else if (b < 4864) { X = X2; H = H2; base = b - 4608; }
    else               { X = X3; H = H3; base = b - 4864; }
    int i0 = base * 4096 + threadIdx.x * 8;
    // two independent 32B chunks -> MLP=4 front-batched loads
    float4 a0 = *reinterpret_cast<const float4*>(X + i0);
    float4 c0 = *reinterpret_cast<const float4*>(X + i0 + 4);
    float4 a1 = *reinterpret_cast<const float4*>(X + i0 + 2048);
    float4 c1 = *reinterpret_cast<const float4*>(X + i0 + 2052);
    __align__(16) __half h0[8], h1[8];
    h0[0] = __float2half_rn(a0.x); h0[1] = __float2half_rn(a0.y);
    h0[2] = __float2half_rn(a0.z); h0[3] = __float2half_rn(a0.w);
    h0[4] = __float2half_rn(c0.x); h0[5] = __float2half_rn(c0.y);
    h0[6] = __float2half_rn(c0.z); h0[7] = __float2half_rn(c0.w);
    h1[0] = __float2half_rn(a1.x); h1[1] = __float2half_rn(a1.y);
    h1[2] = __float2half_rn(a1.z); h1[3] = __float2half_rn(a1.w);
    h1[4] = __float2half_rn(c1.x); h1[5] = __float2half_rn(c1.y);
    h1[6] = __float2half_rn(c1.z); h1[7] = __float2half_rn(c1.w);
    *reinterpret_cast<uint4*>(H + i0)        = *reinterpret_cast<uint4*>(h0);
    *reinterpret_cast<uint4*>(H + i0 + 2048) = *reinterpret_cast<uint4*>(h1);
}

// ---------------- fp16 mma.sync GEMM: C[M,N] = A[M,K]@W[N,K]^T + bias ----------
// 128x128 tile/CTA, 8 warps (4x2 -> 32x64/warp), KC=32 double-buffered cp.async.
#define KC 32
#define ROW_B 80                        // bytes/row: 64B data + 16B pad (ldmatrix conflict-free)
#define COMP_BYTES (128 * ROW_B)        // 10240
#define STAGE_BYTES (2 * COMP_BYTES)    // 20480: A, B
#define GEMM_SMEM (2 * STAGE_BYTES)     // 40960

template <bool FUSE_LOSS>
__global__ __launch_bounds__(256, 2)
void mma_gemm_kernel(const __half* __restrict__ A, const __half* __restrict__ B,
                     const float* __restrict__ bias, float* __restrict__ C,
                     const float* __restrict__ Xref, int N, int K)
{
    extern __shared__ char smem_raw[];
    const uint32_t sbase = smem_u32(smem_raw);
    __shared__ float sred[8];

    const int tid  = threadIdx.x;
    const int wid  = tid >> 5;
    const int lane = tid & 31;
    const int bn = blockIdx.x * 128;
    const int bm = blockIdx.y * 128;
    const int warp_m = wid & 3;         // 0..3 -> 32 rows each
    const int warp_n = wid >> 2;        // 0..1 -> 64 cols each

    const __half* srcA = A + (size_t)bm * K;
    const __half* srcB = B + (size_t)bn * K;

    auto load_stage = [&](int c, int s) {
        const uint32_t st = sbase + (uint32_t)s * STAGE_BYTES;
        const int kbase = c * KC;
        #pragma unroll
        for (int h = 0; h < 2; ++h) {           // A: 512 16B-chunks
            int ch = tid + h * 256;
            int row = ch >> 2, part = ch & 3;
            cp_async16(st + row * ROW_B + part * 16,
                       srcA + (size_t)row * K + kbase + part * 8);
        }
        #pragma unroll
        for (int h = 0; h < 2; ++h) {           // B
            int ch = tid + h * 256;
            int row = ch >> 2, part = ch & 3;
            cp_async16(st + COMP_BYTES + row * ROW_B + part * 16,
                       srcB + (size_t)row * K + kbase + part * 8);
        }
        cp_commit();
    };

    // fragment accumulators: [m-tile 0..1][n-tile 0..7][4]
    float acc[2][8][4];
    #pragma unroll
    for (int i = 0; i < 2; i++)
        #pragma unroll
        for (int j = 0; j < 8; j++)
            #pragma unroll
            for (int q = 0; q < 4; q++) acc[i][j][q] = 0.f;

    // per-thread ldmatrix base offsets
    const int a_row = warp_m * 32 + (lane & 15);
    const int a_k   = (lane >> 4) * 8;
    const int b_row = warp_n * 64 + ((lane >> 3) & 2) * 4 + (lane & 7);
    const int b_k   = ((lane >> 3) & 1) * 8;

    const int nch = K / KC;
    load_stage(0, 0);

    for (int c = 0; c < nch; ++c) {
        if (c + 1 < nch) { load_stage(c + 1, (c + 1) & 1); cp_wait1(); }
        else             { cp_wait0(); }
        __syncthreads();

        const uint32_t st = sbase + (uint32_t)(c & 1) * STAGE_BYTES;
        const uint32_t sA = st;
        const uint32_t sB = st + COMP_BYTES;

        #pragma unroll
        for (int ks = 0; ks < 2; ++ks) {
            uint32_t af[2][4];
            #pragma unroll
            for (int mt = 0; mt < 2; ++mt) {
                uint32_t offA = (uint32_t)((a_row + mt * 16) * ROW_B + (a_k + ks * 16) * 2);
                ldm_x4(af[mt], sA + offA);
            }
            #pragma unroll
            for (int np = 0; np < 4; ++np) {
                uint32_t offB = (uint32_t)((b_row + np * 16) * ROW_B + (b_k + ks * 16) * 2);
                uint32_t bf[4];
                ldm_x4(bf, sB + offB);
                #pragma unroll
                for (int mt = 0; mt < 2; ++mt) {
                    mma_fp16(acc[mt][np * 2 + 0], af[mt], bf + 0);
                    mma_fp16(acc[mt][np * 2 + 1], af[mt], bf + 2);
                }
            }
        }
        __syncthreads();
    }

    // ---------------- epilogue: bias add (+ optional recon loss) ----------------
    const int m0 = bm + warp_m * 32;
    const int n0 = bn + warp_n * 64;
    const int rr = lane >> 2;
    const int cq = (lane & 3) * 2;
    float lsum = 0.f;
    #pragma unroll
    for (int mt = 0; mt < 2; ++mt) {
        #pragma unroll
        for (int nt = 0; nt < 8; ++nt) {
            const int m = m0 + mt * 16 + rr;
            const int n = n0 + nt * 8 + cq;
            float2 bv = *reinterpret_cast<const float2*>(bias + n);
            float2 o0 = make_float2(acc[mt][nt][0] + bv.x, acc[mt][nt][1] + bv.y);
            float2 o1 = make_float2(acc[mt][nt][2] + bv.x, acc[mt][nt][3] + bv.y);
            if (FUSE_LOSS) {
                float2 x0 = *reinterpret_cast<const float2*>(Xref + (size_t)m * N + n);
                float2 x1 = *reinterpret_cast<const float2*>(Xref + (size_t)(m + 8) * N + n);
                float d0 = o0.x - x0.x, d1 = o0.y - x0.y;
                float d2 = o1.x - x1.x, d3 = o1.y - x1.y;
                lsum = fmaf(d0, d0, fmaf(d1, d1, fmaf(d2, d2, fmaf(d3, d3, lsum))));
            }
            *reinterpret_cast<float2*>(C + (size_t)m * N + n) = o0;
            *reinterpret_cast<float2*>(C + (size_t)(m + 8) * N + n) = o1;
        }
    }
    if (FUSE_LOSS) {
        #pragma unroll
        for (int o = 16; o; o >>= 1) lsum += __shfl_xor_sync(0xffffffffu, lsum, o);
        if (lane == 0) sred[wid] = lsum;
        __syncthreads();
        if (tid == 0) {
            float t = 0.f;
            #pragma unroll
            for (int w = 0; w < 8; w++) t += sred[w];
            atomicAdd(&g_recon_sum, (double)t);
        }
    }
}

// ---------------- encoder LN(2L) + KL partial + causal DAG mix, fused --------------
// 256 threads/row; float4 LN loads; causal mix from a register-cached column.
__global__ __launch_bounds__(256)
void ln_enc_causal_kernel(const float* __restrict__ gam, const float* __restrict__ bet)
{
    const int row = blockIdx.x;
    const int tid = threadIdx.x;
    const int lane = tid & 31, wid = tid >> 5;
    __shared__ float zrow[1024];
    __shared__ float dag_sh[256];
    __shared__ float red[8], red2[8], redkl[8];

    dag_sh[tid] = g_dag[tid];

    const float* h = g_h + (size_t)row * L2DIM;
    const float4 v0 = *reinterpret_cast<const float4*>(h + tid * 4);          // mu
    const float4 v1 = *reinterpret_cast<const float4*>(h + 1024 + tid * 4);   // logvar
    float s  = (v0.x + v0.y) + (v0.z + v0.w) + (v1.x + v1.y) + (v1.z + v1.w);
    float s2 = fmaf(v0.x, v0.x, fmaf(v0.y, v0.y, fmaf(v0.z, v0.z, v0.w * v0.w)));
    s2 = fmaf(v1.x, v1.x, fmaf(v1.y, v1.y, fmaf(v1.z, v1.z, fmaf(v1.w, v1.w, s2))));
    #pragma unroll
    for (int o = 16; o; o >>= 1) {
        s  += __shfl_xor_sync(0xffffffffu, s, o);
        s2 += __shfl_xor_sync(0xffffffffu, s2, o);
    }
    if (lane == 0) { red[wid] = s; red2[wid] = s2; }
    __syncthreads();
    if (tid < 32) {
        float a = (tid < 8) ? red[tid] : 0.f;
        float b = (tid < 8) ? red2[tid] : 0.f;
        #pragma unroll
        for (int o = 4; o; o >>= 1) {
            a += __shfl_xor_sync(0xffffffffu, a, o);
            b += __shfl_xor_sync(0xffffffffu, b, o);
        }
        if (tid == 0) { red[0] = a; red2[0] = b; }
    }
    __syncthreads();
    const float mean = red[0] * (1.f / 2048.f);
    const float var  = red2[0] * (1.f / 2048.f) - mean * mean;
    const float rstd = rsqrtf(var + 1e-5f);

    const float4 g0 = *reinterpret_cast<const float4*>(gam + tid * 4);
    const float4 b0 = *reinterpret_cast<const float4*>(bet + tid * 4);
    const float4 g1 = *reinterpret_cast<const float4*>(gam + 1024 + tid * 4);
    const float4 b1 = *reinterpret_cast<const float4*>(bet + 1024 + tid * 4);

    float4 y0;   // mu normalized
    y0.x = (v0.x - mean) * rstd * g0.x + b0.x;
    y0.y = (v0.y - mean) * rstd * g0.y + b0.y;
    y0.z = (v0.z - mean) * rstd * g0.z + b0.z;
    y0.w = (v0.w - mean) * rstd * g0.w + b0.w;
    *reinterpret_cast<float4*>(&zrow[tid * 4]) = y0;

    float4 y1;   // logvar normalized
    y1.x = (v1.x - mean) * rstd * g1.x + b1.x;
    y1.y = (v1.y - mean) * rstd * g1.y + b1.y;
    y1.z = (v1.z - mean) * rstd * g1.z + b1.z;
    y1.w = (v1.w - mean) * rstd * g1.w + b1.w;

    float kl = -(y0.x * y0.x + y0.y * y0.y + y0.z * y0.z + y0.w * y0.w)
             + 4.f + (y1.x - expf(y1.x)) + (y1.y - expf(y1.y))
                   + (y1.z - expf(y1.z)) + (y1.w - expf(y1.w));
    #pragma unroll
    for (int o = 16; o; o >>= 1) kl += __shfl_xor_sync(0xffffffffu, kl, o);
    if (lane == 0) redkl[wid] = kl;
    __syncthreads();              // zrow complete + redkl ready
    if (tid == 0) {
        float t = 0.f;
        #pragma unroll
        for (int w = 0; w < 8; w++) t += redkl[w];
        atomicAdd(&g_kl_sum, (double)t);
    }

    // causal: zc[i,e] = z[i,e] + sum_{j<i} dag[i,j]*z[j,e]
    // thread owns column e = tid&63, outputs i = b+4q (b = tid>>6, warp-uniform).
    const int b = tid >> 6, e = tid & 63;
    float zreg[16];
    #pragma unroll
    for (int j = 0; j < 16; ++j) zreg[j] = zrow[(j << 6) + e];   // conflict-free
    #pragma unroll
    for (int q = 0; q < 4; ++q) {
        const int i = b + q * 4;
        float a = zreg[i];
        const float* dr = &dag_sh[i * 16];
        for (int j = 0; j < i; ++j)              // warp-uniform bound, dag broadcast
            a = fmaf(dr[j], zreg[j], a);
        g_zch[(size_t)row * LDIM + (i << 6) + e] = __float2half_rn(a);
    }
}

// ---------------- per-concept via mma: Linear(64) -> LN -> ReLU -> Linear(64) ------
#define CSTRIDE 72      // halves per smem row (144 B -> conflict-free LDSM)

__global__ __launch_bounds__(256)
void concept_mma_kernel(const float* __restrict__ cw1, const float* __restrict__ cb1,
                        const float* __restrict__ cg,  const float* __restrict__ cbt,
                        const float* __restrict__ cw2, const float* __restrict__ cb2,
                        const __half* __restrict__ Z,  __half* __restrict__ Out)
{
    const int c     = blockIdx.y;
    const int rbase = blockIdx.x * 128;
    const int tid   = threadIdx.x;
    const int wid   = tid >> 5;
    const int lane  = tid & 31;

    __shared__ __half w1s[64 * CSTRIDE];
    __shared__ __half w2s[64 * CSTRIDE];
    __shared__ __half zs [128 * CSTRIDE];
    __shared__ float b1s[64], gs[64], bts[64], b2s[64];

    {
        const uint32_t zb = smem_u32(zs);
        #pragma unroll
        for (int h = 0; h < 4; ++h) {
            int i = tid + h * 256;                 // 1024 16B chunks
            int row = i >> 3, part = i & 7;
            cp_async16(zb + row * (CSTRIDE * 2) + part * 16,
                       Z + (size_t)(rbase + row) * LDIM + c * 64 + part * 8);
        }
        cp_commit();
    }
    for (int i = tid; i < 4096; i += 256) {
        int d = i >> 6, e = i & 63;
        w1s[d * CSTRIDE + e] = __float2half_rn(cw1[(size_t)c * 4096 + i]);
        w2s[d * CSTRIDE + e] = __float2half_rn(cw2[(size_t)c * 4096 + i]);
    }
    if (tid < 64) {
        b1s[tid] = cb1[c * 64 + tid];
        gs[tid]  = cg [c * 64 + tid];
        bts[tid] = cbt[c * 64 + tid];
        b2s[tid] = cb2[c * 64 + tid];
    }
    cp_wait0();
    __syncthreads();

    const uint32_t aB = smem_u32(zs)
        + (uint32_t)((wid * 16 + (lane & 15)) * (CSTRIDE * 2) + ((lane >> 4) * 8) * 2);
    uint32_t af[4][4];
    #pragma unroll
    for (int ks = 0; ks < 4; ++ks) ldm_x4(af[ks], aB + ks * 32);

    const int b_row = ((lane >> 3) & 2) * 4 + (lane & 7);
    const int b_k   = ((lane >> 3) & 1) * 8;
    const uint32_t w1B = smem_u32(w1s) + (uint32_t)(b_row * (CSTRIDE * 2) + b_k * 2);
    const uint32_t w2B = smem_u32(w2s) + (uint32_t)(b_row * (CSTRIDE * 2) + b_k * 2);

    float acc[8][4];
    #pragma unroll
    for (int j = 0; j < 8; j++)
        #pragma unroll
        for (int q = 0; q < 4; q++) acc[j][q] = 0.f;

    #pragma unroll
    for (int np = 0; np < 4; ++np) {
        #pragma unroll
        for (int ks = 0; ks < 4; ++ks) {
            uint32_t bf[4];
            ldm_x4(bf, w1B + (uint32_t)(np * 16 * (CSTRIDE * 2) + ks * 32));
            mma_fp16(acc[np * 2 + 0], af[ks], bf + 0);
            mma_fp16(acc[np * 2 + 1], af[ks], bf + 2);
        }
    }

    float s0 = 0.f, q0 = 0.f, s1 = 0.f, q1 = 0.f;
    #pragma unroll
    for (int nt = 0; nt < 8; ++nt) {
        int n = nt * 8 + (lane & 3) * 2;
        float bA = b1s[n], bB = b1s[n + 1];
        acc[nt][0] += bA; acc[nt][1] += bB;
        acc[nt][2] += bA; acc[nt][3] += bB;
        s0 += acc[nt][0] + acc[nt][1];
        q0 = fmaf(acc[nt][0], acc[nt][0], fmaf(acc[nt][1], acc[nt][1], q0));
        s1 += acc[nt][2] + acc[nt][3];
        q1 = fmaf(acc[nt][2], acc[nt][2], fmaf(acc[nt][3], acc[nt][3], q1));
    }
    #pragma unroll
    for (int o = 1; o <= 2; o <<= 1) {
        s0 += __shfl_xor_sync(0xffffffffu, s0, o);
        q0 += __shfl_xor_sync(0xffffffffu, q0, o);
        s1 += __shfl_xor_sync(0xffffffffu, s1, o);
        q1 += __shfl_xor_sync(0xffffffffu, q1, o);
    }
    float m0 = s0 * (1.f / 64.f), v0 = q0 * (1.f / 64.f) - m0 * m0;
    float m1 = s1 * (1.f / 64.f), v1 = q1 * (1.f / 64.f) - m1 * m1;
    float r0 = rsqrtf(v0 + 1e-5f), r1 = rsqrtf(v1 + 1e-5f);

    uint32_t a2[4][4];
    #pragma unroll
    for (int nt = 0; nt < 8; ++nt) {
        int n = nt * 8 + (lane & 3) * 2;
        float gA = gs[n], gB = gs[n + 1], tA = bts[n], tB = bts[n + 1];
        float y00 = fmaxf(fmaf((acc[nt][0] - m0) * r0, gA, tA), 0.f);
        float y01 = fmaxf(fmaf((acc[nt][1] - m0) * r0, gB, tB), 0.f);
        float y10 = fmaxf(fmaf((acc[nt][2] - m1) * r1, gA, tA), 0.f);
        float y11 = fmaxf(fmaf((acc[nt][3] - m1) * r1, gB, tB), 0.f);
        __half2 h0 = __floats2half2_rn(y00, y01);
        __half2 h1 = __floats2half2_rn(y10, y11);
        int kt = nt >> 1;
        if ((nt & 1) == 0) {
            a2[kt][0] = *reinterpret_cast<uint32_t*>(&h0);
            a2[kt][1] = *reinterpret_cast<uint32_t*>(&h1);
        } else {
            a2[kt][2] = *reinterpret_cast<uint32_t*>(&h0);
            a2[kt][3] = *reinterpret_cast<uint32_t*>(&h1);
        }
    }

    float acc2[8][4];
    #pragma unroll
    for (int j = 0; j < 8; j++)
        #pragma unroll
        for (int q = 0; q < 4; q++) acc2[j][q] = 0.f;

    #pragma unroll
    for (int np = 0; np < 4; ++np) {
        #pragma unroll
        for (int ks = 0; ks < 4; ++ks) {
            uint32_t bf[4];
            ldm_x4(bf, w2B + (uint32_t)(np * 16 * (CSTRIDE * 2) + ks * 32));
            mma_fp16(acc2[np * 2 + 0], a2[ks], bf + 0);
            mma_fp16(acc2[np * 2 + 1], a2[ks], bf + 2);
        }
    }

    const int grow = rbase + wid * 16 + (lane >> 2);
    #pragma unroll
    for (int nt = 0; nt < 8; ++nt) {
        int n = nt * 8 + (lane & 3) * 2;
        __half2 o0 = __floats2half2_rn(acc2[nt][0] + b2s[n], acc2[nt][1] + b2s[n + 1]);
        __half2 o1 = __floats2half2_rn(acc2[nt][2] + b2s[n], acc2[nt][3] + b2s[n + 1]);
        *reinterpret_cast<__half2*>(Out + (size_t)grow * LDIM + c * 64 + n) = o0;
        *reinterpret_cast<__half2*>(Out + (size_t)(grow + 8) * LDIM + c * 64 + n) = o1;
    }
}

// ---------------- decoder mid: LN(1024) + ReLU -> fp16 (float4 path) ----------------
__global__ __launch_bounds__(256)
void ln_relu_kernel(const float* __restrict__ X, const float* __restrict__ gam,
                    const float* __restrict__ bet, __half* __restrict__ YH)
{
    const int row = blockIdx.x;
    const int tid = threadIdx.x;
    const int lane = tid & 31, wid = tid >> 5;
    __shared__ float red[8], red2[8];

    const float4 v = *reinterpret_cast<const float4*>(X + (size_t)row * LDIM + tid * 4);
    float s  = v.x + v.y + v.z + v.w;
    float s2 = fmaf(v.x, v.x, fmaf(v.y, v.y, fmaf(v.z, v.z, v.w * v.w)));
    #pragma unroll
    for (int o = 16; o; o >>= 1) {
        s  += __shfl_xor_sync(0xffffffffu, s, o);
        s2 += __shfl_xor_sync(0xffffffffu, s2, o);
    }
    if (lane == 0) { red[wid] = s; red2[wid] = s2; }
    __syncthreads();
    if (tid < 32) {
        float a = (tid < 8) ? red[tid] : 0.f;
        float b = (tid < 8) ? red2[tid] : 0.f;
        #pragma unroll
        for (int o = 4; o; o >>= 1) {
            a += __shfl_xor_sync(0xffffffffu, a, o);
            b += __shfl_xor_sync(0xffffffffu, b, o);
        }
        if (tid == 0) { red[0] = a; red2[0] = b; }
    }
    __syncthreads();
    const float mean = red[0] * (1.f / 1024.f);
    const float var  = red2[0] * (1.f / 1024.f) - mean * mean;
    const float rstd = rsqrtf(var + 1e-5f);

    const float4 gv = *reinterpret_cast<const float4*>(gam + tid * 4);
    const float4 bv = *reinterpret_cast<const float4*>(bet + tid * 4);
    __half2 h0 = __floats2half2_rn(fmaxf((v.x - mean) * rstd * gv.x + bv.x, 0.f),
                                   fmaxf((v.y - mean) * rstd * gv.y + bv.y, 0.f));
    __half2 h1 = __floats2half2_rn(fmaxf((v.z - mean) * rstd * gv.z + bv.z, 0.f),
                                   fmaxf((v.w - mean) * rstd * gv.w + bv.w, 0.f));
    uint2 pk = make_uint2(*reinterpret_cast<uint32_t*>(&h0), *reinterpret_cast<uint32_t*>(&h1));
    *reinterpret_cast<uint2*>(YH + (size_t)row * LDIM + tid * 4) = pk;
}

// ---------------- finalize scalars ----------------
__global__ void finalize_kernel(float* __restrict__ out, long long nout)
{
    double kl    = -0.5 * g_kl_sum / ((double)MDIM * (double)LDIM);
    double recon = g_recon_sum / ((double)MDIM * (double)DDIM);
    double dagl  = g_dag_loss;
    double total = recon + 0.3 * kl + 1.0 * dagl;
    long long base = (long long)MDIM * DDIM;
    if (nout >= base + 4) {
        out[base + 0] = (float)total;
        out[base + 1] = (float)kl;
        out[base + 2] = (float)recon;
        out[base + 3] = (float)dagl;
    }
}

// ---------------- launch ----------------
extern "C" void kernel_launch(void* const* d_in, const int* in_sizes, int n_in,
                              void* d_out, int out_size)
{
    (void)in_sizes; (void)n_in;
    const float* x      = (const float*)d_in[0];
    const float* enc_w  = (const float*)d_in[1];
    const float* enc_b  = (const float*)d_in[2];
    const float* enc_g  = (const float*)d_in[3];
    const float* enc_bt = (const float*)d_in[4];
    const float* dag_w  = (const float*)d_in[5];
    const float* cw1    = (const float*)d_in[6];
    const float* cb1    = (const float*)d_in[7];
    const float* cg     = (const float*)d_in[8];
    const float* cbt    = (const float*)d_in[9];
    const float* cw2    = (const float*)d_in[10];
    const float* cb2    = (const float*)d_in[11];
    const float* dec_w1 = (const float*)d_in[12];
    const float* dec_b1 = (const float*)d_in[13];
    const float* dec_g  = (const float*)d_in[14];
    const float* dec_bt = (const float*)d_in[15];
    const float* dec_w2 = (const float*)d_in[16];
    const float* dec_b2 = (const float*)d_in[17];
    float* out = (float*)d_out;

    float *ph, *pdd;
    __half *pxh, *pewh, *pzch, *pzth, *pdh, *pw1h, *pw2h;
    cudaGetSymbolAddress((void**)&ph,   g_h);
    cudaGetSymbolAddress((void**)&pdd,  g_dd);
    cudaGetSymbolAddress((void**)&pxh,  g_xh);
    cudaGetSymbolAddress((void**)&pewh, g_ewh);
    cudaGetSymbolAddress((void**)&pzch, g_zch);
    cudaGetSymbolAddress((void**)&pzth, g_zth);
    cudaGetSymbolAddress((void**)&pdh,  g_dh);
    cudaGetSymbolAddress((void**)&pw1h, g_w1h);
    cudaGetSymbolAddress((void**)&pw2h, g_w2h);

    cudaFuncSetAttribute(mma_gemm_kernel<false>,
                         cudaFuncAttributeMaxDynamicSharedMemorySize, GEMM_SMEM);
    cudaFuncSetAttribute(mma_gemm_kernel<true>,
                         cudaFuncAttributeMaxDynamicSharedMemorySize, GEMM_SMEM);

    // dag + loss-acc init
    dag_kernel<<<1, 256>>>(dag_w);
    // all fp32 -> fp16 conversions in one launch (2-way ILP)
    conv_all_kernel<<<5120, 256>>>(x, pxh, enc_w, pewh, dec_w1, pw1h, dec_w2, pw2h);
    // encoder: h = x @ enc_w^T + enc_b   [16384, 2048]
    mma_gemm_kernel<false><<<dim3(L2DIM / 128, MDIM / 128), 256, GEMM_SMEM>>>(
        pxh, pewh, enc_b, ph, nullptr, L2DIM, DDIM);
    // LN(2L) + KL + causal mix -> fp16 g_zch
    ln_enc_causal_kernel<<<MDIM, 256>>>(enc_g, enc_bt);
    // per-concept transform via mma -> fp16 g_zth
    concept_mma_kernel<<<dim3(MDIM / 128, CN), 256>>>(cw1, cb1, cg, cbt, cw2, cb2,
                                                      pzch, pzth);
    // decoder GEMM 1 -> g_dd
    mma_gemm_kernel<false><<<dim3(LDIM / 128, MDIM / 128), 256, GEMM_SMEM>>>(
        pzth, pw1h, dec_b1, pdd, nullptr, LDIM, LDIM);
    // LN + ReLU -> fp16 g_d
    ln_relu_kernel<<<MDIM, 256>>>(pdd, dec_g, dec_bt, pdh);
    // decoder GEMM 2 -> x_recon (d_out) + fused recon loss
    mma_gemm_kernel<true><<<dim3(DDIM / 128, MDIM / 128), 256, GEMM_SMEM>>>(
        pdh, pw2h, dec_b2, out, x, DDIM, LDIM);
    // scalars
    finalize_kernel<<<1, 1>>>(out, (long long)out_size);
}

// round 10
// speedup vs baseline: 1.0233x; 1.0233x over previous
#include <cuda_runtime.h>
#include <cuda_fp16.h>
#include <math.h>
#include <stdint.h>

// ---------------- problem dims ----------------
#define MDIM 16384          // B*S
#define DDIM 1024           // input dim
#define LDIM 1024           // latent
#define L2DIM 2048          // 2L
#define CN 16               // concepts

// ---------------- scratch (device globals; no allocation) ----------------
__device__ float g_h [(size_t)MDIM * L2DIM];    // encoder pre-LN output
__device__ float g_dd[(size_t)MDIM * LDIM];     // decoder mid pre-LN
__device__ __half g_zch[(size_t)MDIM * LDIM];   // z_causal fp16
__device__ __half g_xh [(size_t)MDIM * DDIM];   // x in fp16
__device__ __half g_zth[(size_t)MDIM * LDIM];   // concept out fp16
__device__ __half g_dh [(size_t)MDIM * LDIM];   // decoder mid fp16
__device__ __half g_ewh[(size_t)L2DIM * DDIM];  // enc_w fp16
__device__ __half g_w1h[(size_t)LDIM * LDIM];   // dec_w1 fp16
__device__ __half g_w2h[(size_t)DDIM * LDIM];   // dec_w2 fp16
__device__ float g_dag[CN * CN];
__device__ double g_kl_sum;
__device__ double g_recon_sum;
__device__ double g_dag_loss;

// ---------------- PTX helpers (baseline ISA only — no tcgen05 on sm_103) ----------
__device__ __forceinline__ uint32_t smem_u32(const void* p) {
    return (uint32_t)__cvta_generic_to_shared(p);
}
__device__ __forceinline__ void cp_async16(uint32_t dst, const void* src) {
    asm volatile("cp.async.cg.shared.global [%0], [%1], 16;" :: "r"(dst), "l"(src));
}
__device__ __forceinline__ void cp_commit() {
    asm volatile("cp.async.commit_group;" ::: "memory");
}
__device__ __forceinline__ void cp_wait1() {
    asm volatile("cp.async.wait_group 1;" ::: "memory");
}
__device__ __forceinline__ void cp_wait0() {
    asm volatile("cp.async.wait_group 0;" ::: "memory");
}
__device__ __forceinline__ void ldm_x4(uint32_t* r, uint32_t addr) {
    asm volatile("ldmatrix.sync.aligned.m8n8.x4.shared.b16 {%0,%1,%2,%3}, [%4];"
                 : "=r"(r[0]), "=r"(r[1]), "=r"(r[2]), "=r"(r[3]) : "r"(addr));
}
__device__ __forceinline__ void mma_fp16(float* c, const uint32_t* a, const uint32_t* b) {
    asm volatile(
        "mma.sync.aligned.m16n8k16.row.col.f32.f16.f16.f32 "
        "{%0,%1,%2,%3}, {%4,%5,%6,%7}, {%8,%9}, {%0,%1,%2,%3};"
        : "+f"(c[0]), "+f"(c[1]), "+f"(c[2]), "+f"(c[3])
        : "r"(a[0]), "r"(a[1]), "r"(a[2]), "r"(a[3]), "r"(b[0]), "r"(b[1]));
}

// ---------------- dag (+ loss-accumulator init) ----------------
// trace(expm(dag)) == C exactly (dag strictly lower triangular -> nilpotent).
__global__ void dag_kernel(const float* __restrict__ dag_w) {
    int tid = threadIdx.x;            // 256 threads
    int i = tid >> 4, j = tid & 15;
    float v = 0.f;
    if (i > j) {
        float x = dag_w[tid];
        v = (x > 20.f) ? x : log1pf(expf(x));
    }
    g_dag[tid] = v;
    __shared__ float sh[8];
    float s = v;
    #pragma unroll
    for (int o = 16; o; o >>= 1) s += __shfl_xor_sync(0xffffffffu, s, o);
    if ((tid & 31) == 0) sh[tid >> 5] = s;
    __syncthreads();
    if (tid == 0) {
        float t = 0.f;
        #pragma unroll
        for (int w = 0; w < 8; w++) t += sh[w];
        g_dag_loss = (double)t + 16.0;
        g_kl_sum = 0.0;
        g_recon_sum = 0.0;
    }
}

// ---------------- fp32 -> fp16 convert, all 4 arrays, 2-way ILP ----------------
// block handles 4096 elems: [0,4096) x | [4096,4608) enc_w | [4608,4864) w1 | [4864,5120) w2
__global__ __launch_bounds__(256)
void conv_all_kernel(const float* __restrict__ X0, __half* __restrict__ H0,
                     const float* __restrict__ X1, __half* __restrict__ H1,
                     const float* __restrict__ X2, __half* __restrict__ H2,
                     const float* __restrict__ X3, __half* __restrict__ H3)
{
    int b = blockIdx.x;
    const float* X; __half* H; int base;
    if (b < 4096)      { X = X0; H = H0; base = b; }
    else if (b < 4608) { X = X1; H = H1; base = b - 4096; }
    else if (b < 4864) { X = X2; H = H2; base = b - 4608; }
    else               { X = X3; H = H3; base = b - 4864; }
    int i0 = base * 4096 + threadIdx.x * 8;
    float4 a0 = *reinterpret_cast<const float4*>(X + i0);
    float4 c0 = *reinterpret_cast<const float4*>(X + i0 + 4);
    float4 a1 = *reinterpret_cast<const float4*>(X + i0 + 2048);
    float4 c1 = *reinterpret_cast<const float4*>(X + i0 + 2052);
    __align__(16) __half h0[8], h1[8];
    h0[0] = __float2half_rn(a0.x); h0[1] = __float2half_rn(a0.y);
    h0[2] = __float2half_rn(a0.z); h0[3] = __float2half_rn(a0.w);
    h0[4] = __float2half_rn(c0.x); h0[5] = __float2half_rn(c0.y);
    h0[6] = __float2half_rn(c0.z); h0[7] = __float2half_rn(c0.w);
    h1[0] = __float2half_rn(a1.x); h1[1] = __float2half_rn(a1.y);
    h1[2] = __float2half_rn(a1.z); h1[3] = __float2half_rn(a1.w);
    h1[4] = __float2half_rn(c1.x); h1[5] = __float2half_rn(c1.y);
    h1[6] = __float2half_rn(c1.z); h1[7] = __float2half_rn(c1.w);
    *reinterpret_cast<uint4*>(H + i0)        = *reinterpret_cast<uint4*>(h0);
    *reinterpret_cast<uint4*>(H + i0 + 2048) = *reinterpret_cast<uint4*>(h1);
}

// ---------------- fp16 mma.sync GEMM: C[M,N] = A[M,K]@W[N,K]^T + bias ----------
// 128x128 tile/CTA, 8 warps (4x2 -> 32x64/warp), KC=32 double-buffered cp.async.
#define KC 32
#define ROW_B 80                        // bytes/row: 64B data + 16B pad (ldmatrix conflict-free)
#define COMP_BYTES (128 * ROW_B)        // 10240
#define STAGE_BYTES (2 * COMP_BYTES)    // 20480: A, B
#define GEMM_SMEM (2 * STAGE_BYTES)     // 40960

template <bool FUSE_LOSS>
__global__ __launch_bounds__(256, 2)
void mma_gemm_kernel(const __half* __restrict__ A, const __half* __restrict__ B,
                     const float* __restrict__ bias, float* __restrict__ C,
                     const float* __restrict__ Xref, int N, int K)
{
    extern __shared__ char smem_raw[];
    const uint32_t sbase = smem_u32(smem_raw);
    __shared__ float sred[8];

    const int tid  = threadIdx.x;
    const int wid  = tid >> 5;
    const int lane = tid & 31;
    const int bn = blockIdx.x * 128;
    const int bm = blockIdx.y * 128;
    const int warp_m = wid & 3;         // 0..3 -> 32 rows each
    const int warp_n = wid >> 2;        // 0..1 -> 64 cols each

    const __half* srcA = A + (size_t)bm * K;
    const __half* srcB = B + (size_t)bn * K;

    auto load_stage = [&](int c, int s) {
        const uint32_t st = sbase + (uint32_t)s * STAGE_BYTES;
        const int kbase = c * KC;
        #pragma unroll
        for (int h = 0; h < 2; ++h) {           // A: 512 16B-chunks
            int ch = tid + h * 256;
            int row = ch >> 2, part = ch & 3;
            cp_async16(st + row * ROW_B + part * 16,
                       srcA + (size_t)row * K + kbase + part * 8);
        }
        #pragma unroll
        for (int h = 0; h < 2; ++h) {           // B
            int ch = tid + h * 256;
            int row = ch >> 2, part = ch & 3;
            cp_async16(st + COMP_BYTES + row * ROW_B + part * 16,
                       srcB + (size_t)row * K + kbase + part * 8);
        }
        cp_commit();
    };

    // fragment accumulators: [m-tile 0..1][n-tile 0..7][4]
    float acc[2][8][4];
    #pragma unroll
    for (int i = 0; i < 2; i++)
        #pragma unroll
        for (int j = 0; j < 8; j++)
            #pragma unroll
            for (int q = 0; q < 4; q++) acc[i][j][q] = 0.f;

    // per-thread ldmatrix base offsets
    const int a_row = warp_m * 32 + (lane & 15);
    const int a_k   = (lane >> 4) * 8;
    const int b_row = warp_n * 64 + ((lane >> 3) & 2) * 4 + (lane & 7);
    const int b_k   = ((lane >> 3) & 1) * 8;

    const int nch = K / KC;
    load_stage(0, 0);

    for (int c = 0; c < nch; ++c) {
        if (c + 1 < nch) { load_stage(c + 1, (c + 1) & 1); cp_wait1(); }
        else             { cp_wait0(); }
        __syncthreads();

        const uint32_t st = sbase + (uint32_t)(c & 1) * STAGE_BYTES;
        const uint32_t sA = st;
        const uint32_t sB = st + COMP_BYTES;

        #pragma unroll
        for (int ks = 0; ks < 2; ++ks) {
            uint32_t af[2][4];
            #pragma unroll
            for (int mt = 0; mt < 2; ++mt) {
                uint32_t offA = (uint32_t)((a_row + mt * 16) * ROW_B + (a_k + ks * 16) * 2);
                ldm_x4(af[mt], sA + offA);
            }
            #pragma unroll
            for (int np = 0; np < 4; ++np) {
                uint32_t offB = (uint32_t)((b_row + np * 16) * ROW_B + (b_k + ks * 16) * 2);
                uint32_t bf[4];
                ldm_x4(bf, sB + offB);
                #pragma unroll
                for (int mt = 0; mt < 2; ++mt) {
                    mma_fp16(acc[mt][np * 2 + 0], af[mt], bf + 0);
                    mma_fp16(acc[mt][np * 2 + 1], af[mt], bf + 2);
                }
            }
        }
        __syncthreads();
    }

    // ---------------- epilogue: bias add (+ optional recon loss) ----------------
    const int m0 = bm + warp_m * 32;
    const int n0 = bn + warp_n * 64;
    const int rr = lane >> 2;
    const int cq = (lane & 3) * 2;
    float lsum = 0.f;
    #pragma unroll
    for (int mt = 0; mt < 2; ++mt) {
        #pragma unroll
        for (int nt = 0; nt < 8; ++nt) {
            const int m = m0 + mt * 16 + rr;
            const int n = n0 + nt * 8 + cq;
            float2 bv = *reinterpret_cast<const float2*>(bias + n);
            float2 o0 = make_float2(acc[mt][nt][0] + bv.x, acc[mt][nt][1] + bv.y);
            float2 o1 = make_float2(acc[mt][nt][2] + bv.x, acc[mt][nt][3] + bv.y);
            if (FUSE_LOSS) {
                float2 x0 = *reinterpret_cast<const float2*>(Xref + (size_t)m * N + n);
                float2 x1 = *reinterpret_cast<const float2*>(Xref + (size_t)(m + 8) * N + n);
                float d0 = o0.x - x0.x, d1 = o0.y - x0.y;
                float d2 = o1.x - x1.x, d3 = o1.y - x1.y;
                lsum = fmaf(d0, d0, fmaf(d1, d1, fmaf(d2, d2, fmaf(d3, d3, lsum))));
            }
            *reinterpret_cast<float2*>(C + (size_t)m * N + n) = o0;
            *reinterpret_cast<float2*>(C + (size_t)(m + 8) * N + n) = o1;
        }
    }
    if (FUSE_LOSS) {
        #pragma unroll
        for (int o = 16; o; o >>= 1) lsum += __shfl_xor_sync(0xffffffffu, lsum, o);
        if (lane == 0) sred[wid] = lsum;
        __syncthreads();
        if (tid == 0) {
            float t = 0.f;
            #pragma unroll
            for (int w = 0; w < 8; w++) t += sred[w];
            atomicAdd(&g_recon_sum, (double)t);
        }
    }
}

// ---------------- encoder LN(2L) + KL partial + causal DAG mix, fused --------------
// 256 threads/row; float4 LN loads; conflict-free causal smem reads (R7-proven).
__global__ __launch_bounds__(256)
void ln_enc_causal_kernel(const float* __restrict__ gam, const float* __restrict__ bet)
{
    const int row = blockIdx.x;
    const int tid = threadIdx.x;
    const int lane = tid & 31, wid = tid >> 5;
    __shared__ float zrow[1024];
    __shared__ float dag_sh[256];
    __shared__ float red[8], red2[8], redkl[8];

    dag_sh[tid] = g_dag[tid];

    const float* h = g_h + (size_t)row * L2DIM;
    const float4 v0 = *reinterpret_cast<const float4*>(h + tid * 4);          // mu
    const float4 v1 = *reinterpret_cast<const float4*>(h + 1024 + tid * 4);   // logvar
    float s  = (v0.x + v0.y) + (v0.z + v0.w) + (v1.x + v1.y) + (v1.z + v1.w);
    float s2 = fmaf(v0.x, v0.x, fmaf(v0.y, v0.y, fmaf(v0.z, v0.z, v0.w * v0.w)));
    s2 = fmaf(v1.x, v1.x, fmaf(v1.y, v1.y, fmaf(v1.z, v1.z, fmaf(v1.w, v1.w, s2))));
    #pragma unroll
    for (int o = 16; o; o >>= 1) {
        s  += __shfl_xor_sync(0xffffffffu, s, o);
        s2 += __shfl_xor_sync(0xffffffffu, s2, o);
    }
    if (lane == 0) { red[wid] = s; red2[wid] = s2; }
    __syncthreads();
    if (tid < 32) {
        float a = (tid < 8) ? red[tid] : 0.f;
        float b = (tid < 8) ? red2[tid] : 0.f;
        #pragma unroll
        for (int o = 4; o; o >>= 1) {
            a += __shfl_xor_sync(0xffffffffu, a, o);
            b += __shfl_xor_sync(0xffffffffu, b, o);
        }
        if (tid == 0) { red[0] = a; red2[0] = b; }
    }
    __syncthreads();
    const float mean = red[0] * (1.f / 2048.f);
    const float var  = red2[0] * (1.f / 2048.f) - mean * mean;
    const float rstd = rsqrtf(var + 1e-5f);

    const float4 g0 = *reinterpret_cast<const float4*>(gam + tid * 4);
    const float4 b0 = *reinterpret_cast<const float4*>(bet + tid * 4);
    const float4 g1 = *reinterpret_cast<const float4*>(gam + 1024 + tid * 4);
    const float4 b1 = *reinterpret_cast<const float4*>(bet + 1024 + tid * 4);

    float4 y0;   // mu normalized
    y0.x = (v0.x - mean) * rstd * g0.x + b0.x;
    y0.y = (v0.y - mean) * rstd * g0.y + b0.y;
    y0.z = (v0.z - mean) * rstd * g0.z + b0.z;
    y0.w = (v0.w - mean) * rstd * g0.w + b0.w;
    *reinterpret_cast<float4*>(&zrow[tid * 4]) = y0;

    float4 y1;   // logvar normalized
    y1.x = (v1.x - mean) * rstd * g1.x + b1.x;
    y1.y = (v1.y - mean) * rstd * g1.y + b1.y;
    y1.z = (v1.z - mean) * rstd * g1.z + b1.z;
    y1.w = (v1.w - mean) * rstd * g1.w + b1.w;

    // __expf: MUFU-based; ~1e-6 relative error, negligible inside the 16.8M-term mean
    float kl = -(y0.x * y0.x + y0.y * y0.y + y0.z * y0.z + y0.w * y0.w)
             + 4.f + (y1.x - __expf(y1.x)) + (y1.y - __expf(y1.y))
                   + (y1.z - __expf(y1.z)) + (y1.w - __expf(y1.w));
    #pragma unroll
    for (int o = 16; o; o >>= 1) kl += __shfl_xor_sync(0xffffffffu, kl, o);
    if (lane == 0) redkl[wid] = kl;
    __syncthreads();              // zrow complete + redkl ready
    if (tid == 0) {
        float t = 0.f;
        #pragma unroll
        for (int w = 0; w < 8; w++) t += redkl[w];
        atomicAdd(&g_kl_sum, (double)t);
    }

    // causal: zc[i,e] = z[i,e] + sum_{j<i} dag[i,j]*z[j,e]
    // idx = tid + q*256 -> per-warp consecutive e (conflict-free), uniform i.
    #pragma unroll
    for (int q = 0; q < 4; q++) {
        int idx = tid + q * 256;
        int i = idx >> 6, e = idx & 63;
        float a = zrow[idx];
        const float* dr = &dag_sh[i * 16];
        for (int j = 0; j < i; j++) a = fmaf(dr[j], zrow[(j << 6) + e], a);
        g_zch[(size_t)row * LDIM + idx] = __float2half_rn(a);
    }
}

// ---------------- per-concept via mma: Linear(64) -> LN -> ReLU -> Linear(64) ------
#define CSTRIDE 72      // halves per smem row (144 B -> conflict-free LDSM)

__global__ __launch_bounds__(256)
void concept_mma_kernel(const float* __restrict__ cw1, const float* __restrict__ cb1,
                        const float* __restrict__ cg,  const float* __restrict__ cbt,
                        const float* __restrict__ cw2, const float* __restrict__ cb2,
                        const __half* __restrict__ Z,  __half* __restrict__ Out)
{
    const int c     = blockIdx.y;
    const int rbase = blockIdx.x * 128;
    const int tid   = threadIdx.x;
    const int wid   = tid >> 5;
    const int lane  = tid & 31;

    __shared__ __half w1s[64 * CSTRIDE];
    __shared__ __half w2s[64 * CSTRIDE];
    __shared__ __half zs [128 * CSTRIDE];
    __shared__ float b1s[64], gs[64], bts[64], b2s[64];

    {
        const uint32_t zb = smem_u32(zs);
        #pragma unroll
        for (int h = 0; h < 4; ++h) {
            int i = tid + h * 256;                 // 1024 16B chunks
            int row = i >> 3, part = i & 7;
            cp_async16(zb + row * (CSTRIDE * 2) + part * 16,
                       Z + (size_t)(rbase + row) * LDIM + c * 64 + part * 8);
        }
        cp_commit();
    }
    for (int i = tid; i < 4096; i += 256) {
        int d = i >> 6, e = i & 63;
        w1s[d * CSTRIDE + e] = __float2half_rn(cw1[(size_t)c * 4096 + i]);
        w2s[d * CSTRIDE + e] = __float2half_rn(cw2[(size_t)c * 4096 + i]);
    }
    if (tid < 64) {
        b1s[tid] = cb1[c * 64 + tid];
        gs[tid]  = cg [c * 64 + tid];
        bts[tid] = cbt[c * 64 + tid];
        b2s[tid] = cb2[c * 64 + tid];
    }
    cp_wait0();
    __syncthreads();

    const uint32_t aB = smem_u32(zs)
        + (uint32_t)((wid * 16 + (lane & 15)) * (CSTRIDE * 2) + ((lane >> 4) * 8) * 2);
    uint32_t af[4][4];
    #pragma unroll
    for (int ks = 0; ks < 4; ++ks) ldm_x4(af[ks], aB + ks * 32);

    const int b_row = ((lane >> 3) & 2) * 4 + (lane & 7);
    const int b_k   = ((lane >> 3) & 1) * 8;
    const uint32_t w1B = smem_u32(w1s) + (uint32_t)(b_row * (CSTRIDE * 2) + b_k * 2);
    const uint32_t w2B = smem_u32(w2s) + (uint32_t)(b_row * (CSTRIDE * 2) + b_k * 2);

    float acc[8][4];
    #pragma unroll
    for (int j = 0; j < 8; j++)
        #pragma unroll
        for (int q = 0; q < 4; q++) acc[j][q] = 0.f;

    #pragma unroll
    for (int np = 0; np < 4; ++np) {
        #pragma unroll
        for (int ks = 0; ks < 4; ++ks) {
            uint32_t bf[4];
            ldm_x4(bf, w1B + (uint32_t)(np * 16 * (CSTRIDE * 2) + ks * 32));
            mma_fp16(acc[np * 2 + 0], af[ks], bf + 0);
            mma_fp16(acc[np * 2 + 1], af[ks], bf + 2);
        }
    }

    float s0 = 0.f, q0 = 0.f, s1 = 0.f, q1 = 0.f;
    #pragma unroll
    for (int nt = 0; nt < 8; ++nt) {
        int n = nt * 8 + (lane & 3) * 2;
        float bA = b1s[n], bB = b1s[n + 1];
        acc[nt][0] += bA; acc[nt][1] += bB;
        acc[nt][2] += bA; acc[nt][3] += bB;
        s0 += acc[nt][0] + acc[nt][1];
        q0 = fmaf(acc[nt][0], acc[nt][0], fmaf(acc[nt][1], acc[nt][1], q0));
        s1 += acc[nt][2] + acc[nt][3];
        q1 = fmaf(acc[nt][2], acc[nt][2], fmaf(acc[nt][3], acc[nt][3], q1));
    }
    #pragma unroll
    for (int o = 1; o <= 2; o <<= 1) {
        s0 += __shfl_xor_sync(0xffffffffu, s0, o);
        q0 += __shfl_xor_sync(0xffffffffu, q0, o);
        s1 += __shfl_xor_sync(0xffffffffu, s1, o);
        q1 += __shfl_xor_sync(0xffffffffu, q1, o);
    }
    float m0 = s0 * (1.f / 64.f), v0 = q0 * (1.f / 64.f) - m0 * m0;
    float m1 = s1 * (1.f / 64.f), v1 = q1 * (1.f / 64.f) - m1 * m1;
    float r0 = rsqrtf(v0 + 1e-5f), r1 = rsqrtf(v1 + 1e-5f);

    uint32_t a2[4][4];
    #pragma unroll
    for (int nt = 0; nt < 8; ++nt) {
        int n = nt * 8 + (lane & 3) * 2;
        float gA = gs[n], gB = gs[n + 1], tA = bts[n], tB = bts[n + 1];
        float y00 = fmaxf(fmaf((acc[nt][0] - m0) * r0, gA, tA), 0.f);
        float y01 = fmaxf(fmaf((acc[nt][1] - m0) * r0, gB, tB), 0.f);
        float y10 = fmaxf(fmaf((acc[nt][2] - m1) * r1, gA, tA), 0.f);
        float y11 = fmaxf(fmaf((acc[nt][3] - m1) * r1, gB, tB), 0.f);
        __half2 h0 = __floats2half2_rn(y00, y01);
        __half2 h1 = __floats2half2_rn(y10, y11);
        int kt = nt >> 1;
        if ((nt & 1) == 0) {
            a2[kt][0] = *reinterpret_cast<uint32_t*>(&h0);
            a2[kt][1] = *reinterpret_cast<uint32_t*>(&h1);
        } else {
            a2[kt][2] = *reinterpret_cast<uint32_t*>(&h0);
            a2[kt][3] = *reinterpret_cast<uint32_t*>(&h1);
        }
    }

    float acc2[8][4];
    #pragma unroll
    for (int j = 0; j < 8; j++)
        #pragma unroll
        for (int q = 0; q < 4; q++) acc2[j][q] = 0.f;

    #pragma unroll
    for (int np = 0; np < 4; ++np) {
        #pragma unroll
        for (int ks = 0; ks < 4; ++ks) {
            uint32_t bf[4];
            ldm_x4(bf, w2B + (uint32_t)(np * 16 * (CSTRIDE * 2) + ks * 32));
            mma_fp16(acc2[np * 2 + 0], a2[ks], bf + 0);
            mma_fp16(acc2[np * 2 + 1], a2[ks], bf + 2);
        }
    }

    const int grow = rbase + wid * 16 + (lane >> 2);
    #pragma unroll
    for (int nt = 0; nt < 8; ++nt) {
        int n = nt * 8 + (lane & 3) * 2;
        __half2 o0 = __floats2half2_rn(acc2[nt][0] + b2s[n], acc2[nt][1] + b2s[n + 1]);
        __half2 o1 = __floats2half2_rn(acc2[nt][2] + b2s[n], acc2[nt][3] + b2s[n + 1]);
        *reinterpret_cast<__half2*>(Out + (size_t)grow * LDIM + c * 64 + n) = o0;
        *reinterpret_cast<__half2*>(Out + (size_t)(grow + 8) * LDIM + c * 64 + n) = o1;
    }
}

// ---------------- decoder mid: LN(1024) + ReLU -> fp16 (float4 path) ----------------
__global__ __launch_bounds__(256)
void ln_relu_kernel(const float* __restrict__ X, const float* __restrict__ gam,
                    const float* __restrict__ bet, __half* __restrict__ YH)
{
    const int row = blockIdx.x;
    const int tid = threadIdx.x;
    const int lane = tid & 31, wid = tid >> 5;
    __shared__ float red[8], red2[8];

    const float4 v = *reinterpret_cast<const float4*>(X + (size_t)row * LDIM + tid * 4);
    float s  = v.x + v.y + v.z + v.w;
    float s2 = fmaf(v.x, v.x, fmaf(v.y, v.y, fmaf(v.z, v.z, v.w * v.w)));
    #pragma unroll
    for (int o = 16; o; o >>= 1) {
        s  += __shfl_xor_sync(0xffffffffu, s, o);
        s2 += __shfl_xor_sync(0xffffffffu, s2, o);
    }
    if (lane == 0) { red[wid] = s; red2[wid] = s2; }
    __syncthreads();
    if (tid < 32) {
        float a = (tid < 8) ? red[tid] : 0.f;
        float b = (tid < 8) ? red2[tid] : 0.f;
        #pragma unroll
        for (int o = 4; o; o >>= 1) {
            a += __shfl_xor_sync(0xffffffffu, a, o);
            b += __shfl_xor_sync(0xffffffffu, b, o);
        }
        if (tid == 0) { red[0] = a; red2[0] = b; }
    }
    __syncthreads();
    const float mean = red[0] * (1.f / 1024.f);
    const float var  = red2[0] * (1.f / 1024.f) - mean * mean;
    const float rstd = rsqrtf(var + 1e-5f);

    const float4 gv = *reinterpret_cast<const float4*>(gam + tid * 4);
    const float4 bv = *reinterpret_cast<const float4*>(bet + tid * 4);
    __half2 h0 = __floats2half2_rn(fmaxf((v.x - mean) * rstd * gv.x + bv.x, 0.f),
                                   fmaxf((v.y - mean) * rstd * gv.y + bv.y, 0.f));
    __half2 h1 = __floats2half2_rn(fmaxf((v.z - mean) * rstd * gv.z + bv.z, 0.f),
                                   fmaxf((v.w - mean) * rstd * gv.w + bv.w, 0.f));
    uint2 pk = make_uint2(*reinterpret_cast<uint32_t*>(&h0), *reinterpret_cast<uint32_t*>(&h1));
    *reinterpret_cast<uint2*>(YH + (size_t)row * LDIM + tid * 4) = pk;
}

// ---------------- finalize scalars ----------------
__global__ void finalize_kernel(float* __restrict__ out, long long nout)
{
    double kl    = -0.5 * g_kl_sum / ((double)MDIM * (double)LDIM);
    double recon = g_recon_sum / ((double)MDIM * (double)DDIM);
    double dagl  = g_dag_loss;
    double total = recon + 0.3 * kl + 1.0 * dagl;
    long long base = (long long)MDIM * DDIM;
    if (nout >= base + 4) {
        out[base + 0] = (float)total;
        out[base + 1] = (float)kl;
        out[base + 2] = (float)recon;
        out[base + 3] = (float)dagl;
    }
}

// ---------------- launch ----------------
extern "C" void kernel_launch(void* const* d_in, const int* in_sizes, int n_in,
                              void* d_out, int out_size)
{
    (void)in_sizes; (void)n_in;
    const float* x      = (const float*)d_in[0];
    const float* enc_w  = (const float*)d_in[1];
    const float* enc_b  = (const float*)d_in[2];
    const float* enc_g  = (const float*)d_in[3];
    const float* enc_bt = (const float*)d_in[4];
    const float* dag_w  = (const float*)d_in[5];
    const float* cw1    = (const float*)d_in[6];
    const float* cb1    = (const float*)d_in[7];
    const float* cg     = (const float*)d_in[8];
    const float* cbt    = (const float*)d_in[9];
    const float* cw2    = (const float*)d_in[10];
    const float* cb2    = (const float*)d_in[11];
    const float* dec_w1 = (const float*)d_in[12];
    const float* dec_b1 = (const float*)d_in[13];
    const float* dec_g  = (const float*)d_in[14];
    const float* dec_bt = (const float*)d_in[15];
    const float* dec_w2 = (const float*)d_in[16];
    const float* dec_b2 = (const float*)d_in[17];
    float* out = (float*)d_out;

    float *ph, *pdd;
    __half *pxh, *pewh, *pzch, *pzth, *pdh, *pw1h, *pw2h;
    cudaGetSymbolAddress((void**)&ph,   g_h);
    cudaGetSymbolAddress((void**)&pdd,  g_dd);
    cudaGetSymbolAddress((void**)&pxh,  g_xh);
    cudaGetSymbolAddress((void**)&pewh, g_ewh);
    cudaGetSymbolAddress((void**)&pzch, g_zch);
    cudaGetSymbolAddress((void**)&pzth, g_zth);
    cudaGetSymbolAddress((void**)&pdh,  g_dh);
    cudaGetSymbolAddress((void**)&pw1h, g_w1h);
    cudaGetSymbolAddress((void**)&pw2h, g_w2h);

    cudaFuncSetAttribute(mma_gemm_kernel<false>,
                         cudaFuncAttributeMaxDynamicSharedMemorySize, GEMM_SMEM);
    cudaFuncSetAttribute(mma_gemm_kernel<true>,
                         cudaFuncAttributeMaxDynamicSharedMemorySize, GEMM_SMEM);

    // dag + loss-acc init
    dag_kernel<<<1, 256>>>(dag_w);
    // all fp32 -> fp16 conversions in one launch (2-way ILP)
    conv_all_kernel<<<5120, 256>>>(x, pxh, enc_w, pewh, dec_w1, pw1h, dec_w2, pw2h);
    // encoder: h = x @ enc_w^T + enc_b   [16384, 2048]
    mma_gemm_kernel<false><<<dim3(L2DIM / 128, MDIM / 128), 256, GEMM_SMEM>>>(
        pxh, pewh, enc_b, ph, nullptr, L2DIM, DDIM);
    // LN(2L) + KL + causal mix -> fp16 g_zch
    ln_enc_causal_kernel<<<MDIM, 256>>>(enc_g, enc_bt);
    // per-concept transform via mma -> fp16 g_zth
    concept_mma_kernel<<<dim3(MDIM / 128, CN), 256>>>(cw1, cb1, cg, cbt, cw2, cb2,
                                                      pzch, pzth);
    // decoder GEMM 1 -> g_dd
    mma_gemm_kernel<false><<<dim3(LDIM / 128, MDIM / 128), 256, GEMM_SMEM>>>(
        pzth, pw1h, dec_b1, pdd, nullptr, LDIM, LDIM);
    // LN + ReLU -> fp16 g_d
    ln_relu_kernel<<<MDIM, 256>>>(pdd, dec_g, dec_bt, pdh);
    // decoder GEMM 2 -> x_recon (d_out) + fused recon loss
    mma_gemm_kernel<true><<<dim3(DDIM / 128, MDIM / 128), 256, GEMM_SMEM>>>(
        pdh, pw2h, dec_b2, out, x, DDIM, LDIM);
    // scalars
    finalize_kernel<<<1, 1>>>(out, (long long)out_size);
}

// round 15
// speedup vs baseline: 1.0337x; 1.0101x over previous
#include <cuda_runtime.h>
#include <cuda_fp16.h>
#include <math.h>
#include <stdint.h>

// ---------------- problem dims ----------------
#define MDIM 16384          // B*S
#define DDIM 1024           // input dim
#define LDIM 1024           // latent
#define L2DIM 2048          // 2L
#define CN 16               // concepts

// ---------------- scratch (device globals; no allocation) ----------------
__device__ float g_h [(size_t)MDIM * L2DIM];    // encoder pre-LN output
__device__ float g_dd[(size_t)MDIM * LDIM];     // decoder mid pre-LN
__device__ __half g_zch[(size_t)MDIM * LDIM];   // z_causal fp16
__device__ __half g_xh [(size_t)MDIM * DDIM];   // x in fp16
__device__ __half g_zth[(size_t)MDIM * LDIM];   // concept out fp16
__device__ __half g_dh [(size_t)MDIM * LDIM];   // decoder mid fp16
__device__ __half g_ewh[(size_t)L2DIM * DDIM];  // enc_w fp16
__device__ __half g_w1h[(size_t)LDIM * LDIM];   // dec_w1 fp16
__device__ __half g_w2h[(size_t)DDIM * LDIM];   // dec_w2 fp16
__device__ float g_dag[CN * CN];
__device__ double g_kl_sum;
__device__ double g_recon_sum;
__device__ double g_dag_loss;

// ---------------- PTX helpers (baseline ISA only — no tcgen05 on sm_103) ----------
__device__ __forceinline__ uint32_t smem_u32(const void* p) {
    return (uint32_t)__cvta_generic_to_shared(p);
}
__device__ __forceinline__ void cp_async16(uint32_t dst, const void* src) {
    asm volatile("cp.async.cg.shared.global [%0], [%1], 16;" :: "r"(dst), "l"(src));
}
__device__ __forceinline__ void cp_commit() {
    asm volatile("cp.async.commit_group;" ::: "memory");
}
__device__ __forceinline__ void cp_wait1() {
    asm volatile("cp.async.wait_group 1;" ::: "memory");
}
__device__ __forceinline__ void cp_wait0() {
    asm volatile("cp.async.wait_group 0;" ::: "memory");
}
__device__ __forceinline__ void ldm_x4(uint32_t* r, uint32_t addr) {
    asm volatile("ldmatrix.sync.aligned.m8n8.x4.shared.b16 {%0,%1,%2,%3}, [%4];"
                 : "=r"(r[0]), "=r"(r[1]), "=r"(r[2]), "=r"(r[3]) : "r"(addr));
}
__device__ __forceinline__ void mma_fp16(float* c, const uint32_t* a, const uint32_t* b) {
    asm volatile(
        "mma.sync.aligned.m16n8k16.row.col.f32.f16.f16.f32 "
        "{%0,%1,%2,%3}, {%4,%5,%6,%7}, {%8,%9}, {%0,%1,%2,%3};"
        : "+f"(c[0]), "+f"(c[1]), "+f"(c[2]), "+f"(c[3])
        : "r"(a[0]), "r"(a[1]), "r"(a[2]), "r"(a[3]), "r"(b[0]), "r"(b[1]));
}

// ---------------- dag (+ loss-accumulator init) ----------------
// trace(expm(dag)) == C exactly (dag strictly lower triangular -> nilpotent).
__global__ void dag_kernel(const float* __restrict__ dag_w) {
    int tid = threadIdx.x;            // 256 threads
    int i = tid >> 4, j = tid & 15;
    float v = 0.f;
    if (i > j) {
        float x = dag_w[tid];
        v = (x > 20.f) ? x : log1pf(expf(x));
    }
    g_dag[tid] = v;
    __shared__ float sh[8];
    float s = v;
    #pragma unroll
    for (int o = 16; o; o >>= 1) s += __shfl_xor_sync(0xffffffffu, s, o);
    if ((tid & 31) == 0) sh[tid >> 5] = s;
    __syncthreads();
    if (tid == 0) {
        float t = 0.f;
        #pragma unroll
        for (int w = 0; w < 8; w++) t += sh[w];
        g_dag_loss = (double)t + 16.0;
        g_kl_sum = 0.0;
        g_recon_sum = 0.0;
    }
}

// ---------------- fp32 -> fp16 convert, all 4 arrays, 2-way ILP ----------------
// block handles 4096 elems: [0,4096) x | [4096,4608) enc_w | [4608,4864) w1 | [4864,5120) w2
__global__ __launch_bounds__(256)
void conv_all_kernel(const float* __restrict__ X0, __half* __restrict__ H0,
                     const float* __restrict__ X1, __half* __restrict__ H1,
                     const float* __restrict__ X2, __half* __restrict__ H2,
                     const float* __restrict__ X3, __half* __restrict__ H3)
{
    int b = blockIdx.x;
    const float* X; __half* H; int base;
    if (b < 4096)      { X = X0; H = H0; base = b; }
    else if (b < 4608) { X = X1; H = H1; base = b - 4096; }
    else if (b < 4864) { X = X2; H = H2; base = b - 4608; }
    else               { X = X3; H = H3; base = b - 4864; }
    int i0 = base * 4096 + threadIdx.x * 8;
    float4 a0 = *reinterpret_cast<const float4*>(X + i0);
    float4 c0 = *reinterpret_cast<const float4*>(X + i0 + 4);
    float4 a1 = *reinterpret_cast<const float4*>(X + i0 + 2048);
    float4 c1 = *reinterpret_cast<const float4*>(X + i0 + 2052);
    __align__(16) __half h0[8], h1[8];
    h0[0] = __float2half_rn(a0.x); h0[1] = __float2half_rn(a0.y);
    h0[2] = __float2half_rn(a0.z); h0[3] = __float2half_rn(a0.w);
    h0[4] = __float2half_rn(c0.x); h0[5] = __float2half_rn(c0.y);
    h0[6] = __float2half_rn(c0.z); h0[7] = __float2half_rn(c0.w);
    h1[0] = __float2half_rn(a1.x); h1[1] = __float2half_rn(a1.y);
    h1[2] = __float2half_rn(a1.z); h1[3] = __float2half_rn(a1.w);
    h1[4] = __float2half_rn(c1.x); h1[5] = __float2half_rn(c1.y);
    h1[6] = __float2half_rn(c1.z); h1[7] = __float2half_rn(c1.w);
    *reinterpret_cast<uint4*>(H + i0)        = *reinterpret_cast<uint4*>(h0);
    *reinterpret_cast<uint4*>(H + i0 + 2048) = *reinterpret_cast<uint4*>(h1);
}

// ---------------- fp16 mma.sync GEMM: C[M,N] = A[M,K]@W[N,K]^T + bias ----------
// 128x128 tile/CTA, 8 warps (4x2 -> 32x64/warp), KC=32 double-buffered cp.async.
#define KC 32
#define ROW_B 80                        // bytes/row: 64B data + 16B pad (ldmatrix conflict-free)
#define COMP_BYTES (128 * ROW_B)        // 10240
#define STAGE_BYTES (2 * COMP_BYTES)    // 20480: A, B
#define GEMM_SMEM (2 * STAGE_BYTES)     // 40960

template <bool FUSE_LOSS>
__global__ __launch_bounds__(256, 2)
void mma_gemm_kernel(const __half* __restrict__ A, const __half* __restrict__ B,
                     const float* __restrict__ bias, float* __restrict__ C,
                     const float* __restrict__ Xref, int N, int K)
{
    extern __shared__ char smem_raw[];
    const uint32_t sbase = smem_u32(smem_raw);
    __shared__ float sred[8];

    const int tid  = threadIdx.x;
    const int wid  = tid >> 5;
    const int lane = tid & 31;
    const int bn = blockIdx.x * 128;
    const int bm = blockIdx.y * 128;
    const int warp_m = wid & 3;         // 0..3 -> 32 rows each
    const int warp_n = wid >> 2;        // 0..1 -> 64 cols each

    const __half* srcA = A + (size_t)bm * K;
    const __half* srcB = B + (size_t)bn * K;

    auto load_stage = [&](int c, int s) {
        const uint32_t st = sbase + (uint32_t)s * STAGE_BYTES;
        const int kbase = c * KC;
        #pragma unroll
        for (int h = 0; h < 2; ++h) {           // A: 512 16B-chunks
            int ch = tid + h * 256;
            int row = ch >> 2, part = ch & 3;
            cp_async16(st + row * ROW_B + part * 16,
                       srcA + (size_t)row * K + kbase + part * 8);
        }
        #pragma unroll
        for (int h = 0; h < 2; ++h) {           // B
            int ch = tid + h * 256;
            int row = ch >> 2, part = ch & 3;
            cp_async16(st + COMP_BYTES + row * ROW_B + part * 16,
                       srcB + (size_t)row * K + kbase + part * 8);
        }
        cp_commit();
    };

    // fragment accumulators: [m-tile 0..1][n-tile 0..7][4]
    float acc[2][8][4];
    #pragma unroll
    for (int i = 0; i < 2; i++)
        #pragma unroll
        for (int j = 0; j < 8; j++)
            #pragma unroll
            for (int q = 0; q < 4; q++) acc[i][j][q] = 0.f;

    // per-thread ldmatrix base offsets
    const int a_row = warp_m * 32 + (lane & 15);
    const int a_k   = (lane >> 4) * 8;
    const int b_row = warp_n * 64 + ((lane >> 3) & 2) * 4 + (lane & 7);
    const int b_k   = ((lane >> 3) & 1) * 8;

    const int nch = K / KC;
    load_stage(0, 0);

    for (int c = 0; c < nch; ++c) {
        if (c + 1 < nch) { load_stage(c + 1, (c + 1) & 1); cp_wait1(); }
        else             { cp_wait0(); }
        __syncthreads();

        const uint32_t st = sbase + (uint32_t)(c & 1) * STAGE_BYTES;
        const uint32_t sA = st;
        const uint32_t sB = st + COMP_BYTES;

        #pragma unroll
        for (int ks = 0; ks < 2; ++ks) {
            uint32_t af[2][4];
            #pragma unroll
            for (int mt = 0; mt < 2; ++mt) {
                uint32_t offA = (uint32_t)((a_row + mt * 16) * ROW_B + (a_k + ks * 16) * 2);
                ldm_x4(af[mt], sA + offA);
            }
            #pragma unroll
            for (int np = 0; np < 4; ++np) {
                uint32_t offB = (uint32_t)((b_row + np * 16) * ROW_B + (b_k + ks * 16) * 2);
                uint32_t bf[4];
                ldm_x4(bf, sB + offB);
                #pragma unroll
                for (int mt = 0; mt < 2; ++mt) {
                    mma_fp16(acc[mt][np * 2 + 0], af[mt], bf + 0);
                    mma_fp16(acc[mt][np * 2 + 1], af[mt], bf + 2);
                }
            }
        }
        __syncthreads();
    }

    // ---------------- epilogue: bias add (+ optional recon loss) ----------------
    const int m0 = bm + warp_m * 32;
    const int n0 = bn + warp_n * 64;
    const int rr = lane >> 2;
    const int cq = (lane & 3) * 2;
    float lsum = 0.f;
    #pragma unroll
    for (int mt = 0; mt < 2; ++mt) {
        #pragma unroll
        for (int nt = 0; nt < 8; ++nt) {
            const int m = m0 + mt * 16 + rr;
            const int n = n0 + nt * 8 + cq;
            float2 bv = *reinterpret_cast<const float2*>(bias + n);
            float2 o0 = make_float2(acc[mt][nt][0] + bv.x, acc[mt][nt][1] + bv.y);
            float2 o1 = make_float2(acc[mt][nt][2] + bv.x, acc[mt][nt][3] + bv.y);
            if (FUSE_LOSS) {
                float2 x0 = *reinterpret_cast<const float2*>(Xref + (size_t)m * N + n);
                float2 x1 = *reinterpret_cast<const float2*>(Xref + (size_t)(m + 8) * N + n);
                float d0 = o0.x - x0.x, d1 = o0.y - x0.y;
                float d2 = o1.x - x1.x, d3 = o1.y - x1.y;
                lsum = fmaf(d0, d0, fmaf(d1, d1, fmaf(d2, d2, fmaf(d3, d3, lsum))));
            }
            *reinterpret_cast<float2*>(C + (size_t)m * N + n) = o0;
            *reinterpret_cast<float2*>(C + (size_t)(m + 8) * N + n) = o1;
        }
    }
    if (FUSE_LOSS) {
        #pragma unroll
        for (int o = 16; o; o >>= 1) lsum += __shfl_xor_sync(0xffffffffu, lsum, o);
        if (lane == 0) sred[wid] = lsum;
        __syncthreads();
        if (tid == 0) {
            float t = 0.f;
            #pragma unroll
            for (int w = 0; w < 8; w++) t += sred[w];
            atomicAdd(&g_recon_sum, (double)t);
        }
    }
}

// ---------------- causal mix worker: compile-time P => register-resident column ----
// Thread owns column e; computes outputs i = 4P..4P+3 from z[0..4P+3][e] in regs.
template <int P>
__device__ __forceinline__ void causal_cols(const float* __restrict__ zrow,
                                            const float* __restrict__ dag_sh,
                                            __half* __restrict__ outp, int e)
{
    float zr[4 * P + 4];
    #pragma unroll
    for (int j = 0; j < 4 * P + 4; ++j) zr[j] = zrow[(j << 6) + e];   // conflict-free
    #pragma unroll
    for (int qi = 0; qi < 4; ++qi) {
        float a = zr[4 * P + qi];
        #pragma unroll
        for (int j = 0; j < 4 * P + qi; ++j)
            a = fmaf(dag_sh[(4 * P + qi) * 16 + j], zr[j], a);        // dag broadcast
        outp[((4 * P + qi) << 6) + e] = __float2half_rn(a);
    }
}

// ---------------- encoder LN(2L) + KL partial + causal DAG mix, fused --------------
// 256 threads/row; float4 LN loads; causal mix register-cached per column (P warp-uniform).
__global__ __launch_bounds__(256)
void ln_enc_causal_kernel(const float* __restrict__ gam, const float* __restrict__ bet)
{
    const int row = blockIdx.x;
    const int tid = threadIdx.x;
    const int lane = tid & 31, wid = tid >> 5;
    __shared__ float zrow[1024];
    __shared__ float dag_sh[256];
    __shared__ float red[8], red2[8], redkl[8];

    dag_sh[tid] = g_dag[tid];

    const float* h = g_h + (size_t)row * L2DIM;
    const float4 v0 = *reinterpret_cast<const float4*>(h + tid * 4);          // mu
    const float4 v1 = *reinterpret_cast<const float4*>(h + 1024 + tid * 4);   // logvar
    float s  = (v0.x + v0.y) + (v0.z + v0.w) + (v1.x + v1.y) + (v1.z + v1.w);
    float s2 = fmaf(v0.x, v0.x, fmaf(v0.y, v0.y, fmaf(v0.z, v0.z, v0.w * v0.w)));
    s2 = fmaf(v1.x, v1.x, fmaf(v1.y, v1.y, fmaf(v1.z, v1.z, fmaf(v1.w, v1.w, s2))));
    #pragma unroll
    for (int o = 16; o; o >>= 1) {
        s  += __shfl_xor_sync(0xffffffffu, s, o);
        s2 += __shfl_xor_sync(0xffffffffu, s2, o);
    }
    if (lane == 0) { red[wid] = s; red2[wid] = s2; }
    __syncthreads();
    if (tid < 32) {
        float a = (tid < 8) ? red[tid] : 0.f;
        float b = (tid < 8) ? red2[tid] : 0.f;
        #pragma unroll
        for (int o = 4; o; o >>= 1) {
            a += __shfl_xor_sync(0xffffffffu, a, o);
            b += __shfl_xor_sync(0xffffffffu, b, o);
        }
        if (tid == 0) { red[0] = a; red2[0] = b; }
    }
    __syncthreads();
    const float mean = red[0] * (1.f / 2048.f);
    const float var  = red2[0] * (1.f / 2048.f) - mean * mean;
    const float rstd = rsqrtf(var + 1e-5f);

    const float4 g0 = *reinterpret_cast<const float4*>(gam + tid * 4);
    const float4 b0 = *reinterpret_cast<const float4*>(bet + tid * 4);
    const float4 g1 = *reinterpret_cast<const float4*>(gam + 1024 + tid * 4);
    const float4 b1 = *reinterpret_cast<const float4*>(bet + 1024 + tid * 4);

    float4 y0;   // mu normalized
    y0.x = (v0.x - mean) * rstd * g0.x + b0.x;
    y0.y = (v0.y - mean) * rstd * g0.y + b0.y;
    y0.z = (v0.z - mean) * rstd * g0.z + b0.z;
    y0.w = (v0.w - mean) * rstd * g0.w + b0.w;
    *reinterpret_cast<float4*>(&zrow[tid * 4]) = y0;

    float4 y1;   // logvar normalized
    y1.x = (v1.x - mean) * rstd * g1.x + b1.x;
    y1.y = (v1.y - mean) * rstd * g1.y + b1.y;
    y1.z = (v1.z - mean) * rstd * g1.z + b1.z;
    y1.w = (v1.w - mean) * rstd * g1.w + b1.w;

    // __expf: MUFU-based; ~1e-6 relative error, negligible inside the 16.8M-term mean
    float kl = -(y0.x * y0.x + y0.y * y0.y + y0.z * y0.z + y0.w * y0.w)
             + 4.f + (y1.x - __expf(y1.x)) + (y1.y - __expf(y1.y))
                   + (y1.z - __expf(y1.z)) + (y1.w - __expf(y1.w));
    #pragma unroll
    for (int o = 16; o; o >>= 1) kl += __shfl_xor_sync(0xffffffffu, kl, o);
    if (lane == 0) redkl[wid] = kl;
    __syncthreads();              // zrow complete + redkl ready
    if (tid == 0) {
        float t = 0.f;
        #pragma unroll
        for (int w = 0; w < 8; w++) t += redkl[w];
        atomicAdd(&g_kl_sum, (double)t);
    }

    // causal: zc[i,e] = z[i,e] + sum_{j<i} dag[i,j]*z[j,e]
    // p = tid>>6 is warp-uniform -> compile-time register arrays, no divergence.
    const int p = tid >> 6, e = tid & 63;
    __half* outp = g_zch + (size_t)row * LDIM;
    if (p == 0)      causal_cols<0>(zrow, dag_sh, outp, e);
    else if (p == 1) causal_cols<1>(zrow, dag_sh, outp, e);
    else if (p == 2) causal_cols<2>(zrow, dag_sh, outp, e);
    else             causal_cols<3>(zrow, dag_sh, outp, e);
}

// ---------------- per-concept via mma: Linear(64) -> LN -> ReLU -> Linear(64) ------
#define CSTRIDE 72      // halves per smem row (144 B -> conflict-free LDSM)

__global__ __launch_bounds__(256)
void concept_mma_kernel(const float* __restrict__ cw1, const float* __restrict__ cb1,
                        const float* __restrict__ cg,  const float* __restrict__ cbt,
                        const float* __restrict__ cw2, const float* __restrict__ cb2,
                        const __half* __restrict__ Z,  __half* __restrict__ Out)
{
    const int c     = blockIdx.y;
    const int rbase = blockIdx.x * 128;
    const int tid   = threadIdx.x;
    const int wid   = tid >> 5;
    const int lane  = tid & 31;

    __shared__ __half w1s[64 * CSTRIDE];
    __shared__ __half w2s[64 * CSTRIDE];
    __shared__ __half zs [128 * CSTRIDE];
    __shared__ float b1s[64], gs[64], bts[64], b2s[64];

    {
        const uint32_t zb = smem_u32(zs);
        #pragma unroll
        for (int h = 0; h < 4; ++h) {
            int i = tid + h * 256;                 // 1024 16B chunks
            int row = i >> 3, part = i & 7;
            cp_async16(zb + row * (CSTRIDE * 2) + part * 16,
                       Z + (size_t)(rbase + row) * LDIM + c * 64 + part * 8);
        }
        cp_commit();
    }
    for (int i = tid; i < 4096; i += 256) {
        int d = i >> 6, e = i & 63;
        w1s[d * CSTRIDE + e] = __float2half_rn(cw1[(size_t)c * 4096 + i]);
        w2s[d * CSTRIDE + e] = __float2half_rn(cw2[(size_t)c * 4096 + i]);
    }
    if (tid < 64) {
        b1s[tid] = cb1[c * 64 + tid];
        gs[tid]  = cg [c * 64 + tid];
        bts[tid] = cbt[c * 64 + tid];
        b2s[tid] = cb2[c * 64 + tid];
    }
    cp_wait0();
    __syncthreads();

    const uint32_t aB = smem_u32(zs)
        + (uint32_t)((wid * 16 + (lane & 15)) * (CSTRIDE * 2) + ((lane >> 4) * 8) * 2);
    uint32_t af[4][4];
    #pragma unroll
    for (int ks = 0; ks < 4; ++ks) ldm_x4(af[ks], aB + ks * 32);

    const int b_row = ((lane >> 3) & 2) * 4 + (lane & 7);
    const int b_k   = ((lane >> 3) & 1) * 8;
    const uint32_t w1B = smem_u32(w1s) + (uint32_t)(b_row * (CSTRIDE * 2) + b_k * 2);
    const uint32_t w2B = smem_u32(w2s) + (uint32_t)(b_row * (CSTRIDE * 2) + b_k * 2);

    float acc[8][4];
    #pragma unroll
    for (int j = 0; j < 8; j++)
        #pragma unroll
        for (int q = 0; q < 4; q++) acc[j][q] = 0.f;

    #pragma unroll
    for (int np = 0; np < 4; ++np) {
        #pragma unroll
        for (int ks = 0; ks < 4; ++ks) {
            uint32_t bf[4];
            ldm_x4(bf, w1B + (uint32_t)(np * 16 * (CSTRIDE * 2) + ks * 32));
            mma_fp16(acc[np * 2 + 0], af[ks], bf + 0);
            mma_fp16(acc[np * 2 + 1], af[ks], bf + 2);
        }
    }

    float s0 = 0.f, q0 = 0.f, s1 = 0.f, q1 = 0.f;
    #pragma unroll
    for (int nt = 0; nt < 8; ++nt) {
        int n = nt * 8 + (lane & 3) * 2;
        float bA = b1s[n], bB = b1s[n + 1];
        acc[nt][0] += bA; acc[nt][1] += bB;
        acc[nt][2] += bA; acc[nt][3] += bB;
        s0 += acc[nt][0] + acc[nt][1];
        q0 = fmaf(acc[nt][0], acc[nt][0], fmaf(acc[nt][1], acc[nt][1], q0));
        s1 += acc[nt][2] + acc[nt][3];
        q1 = fmaf(acc[nt][2], acc[nt][2], fmaf(acc[nt][3], acc[nt][3], q1));
    }
    #pragma unroll
    for (int o = 1; o <= 2; o <<= 1) {
        s0 += __shfl_xor_sync(0xffffffffu, s0, o);
        q0 += __shfl_xor_sync(0xffffffffu, q0, o);
        s1 += __shfl_xor_sync(0xffffffffu, s1, o);
        q1 += __shfl_xor_sync(0xffffffffu, q1, o);
    }
    float m0 = s0 * (1.f / 64.f), v0 = q0 * (1.f / 64.f) - m0 * m0;
    float m1 = s1 * (1.f / 64.f), v1 = q1 * (1.f / 64.f) - m1 * m1;
    float r0 = rsqrtf(v0 + 1e-5f), r1 = rsqrtf(v1 + 1e-5f);

    uint32_t a2[4][4];
    #pragma unroll
    for (int nt = 0; nt < 8; ++nt) {
        int n = nt * 8 + (lane & 3) * 2;
        float gA = gs[n], gB = gs[n + 1], tA = bts[n], tB = bts[n + 1];
        float y00 = fmaxf(fmaf((acc[nt][0] - m0) * r0, gA, tA), 0.f);
        float y01 = fmaxf(fmaf((acc[nt][1] - m0) * r0, gB, tB), 0.f);
        float y10 = fmaxf(fmaf((acc[nt][2] - m1) * r1, gA, tA), 0.f);
        float y11 = fmaxf(fmaf((acc[nt][3] - m1) * r1, gB, tB), 0.f);
        __half2 h0 = __floats2half2_rn(y00, y01);
        __half2 h1 = __floats2half2_rn(y10, y11);
        int kt = nt >> 1;
        if ((nt & 1) == 0) {
            a2[kt][0] = *reinterpret_cast<uint32_t*>(&h0);
            a2[kt][1] = *reinterpret_cast<uint32_t*>(&h1);
        } else {
            a2[kt][2] = *reinterpret_cast<uint32_t*>(&h0);
            a2[kt][3] = *reinterpret_cast<uint32_t*>(&h1);
        }
    }

    float acc2[8][4];
    #pragma unroll
    for (int j = 0; j < 8; j++)
        #pragma unroll
        for (int q = 0; q < 4; q++) acc2[j][q] = 0.f;

    #pragma unroll
    for (int np = 0; np < 4; ++np) {
        #pragma unroll
        for (int ks = 0; ks < 4; ++ks) {
            uint32_t bf[4];
            ldm_x4(bf, w2B + (uint32_t)(np * 16 * (CSTRIDE * 2) + ks * 32));
            mma_fp16(acc2[np * 2 + 0], a2[ks], bf + 0);
            mma_fp16(acc2[np * 2 + 1], a2[ks], bf + 2);
        }
    }

    const int grow = rbase + wid * 16 + (lane >> 2);
    #pragma unroll
    for (int nt = 0; nt < 8; ++nt) {
        int n = nt * 8 + (lane & 3) * 2;
        __half2 o0 = __floats2half2_rn(acc2[nt][0] + b2s[n], acc2[nt][1] + b2s[n + 1]);
        __half2 o1 = __floats2half2_rn(acc2[nt][2] + b2s[n], acc2[nt][3] + b2s[n + 1]);
        *reinterpret_cast<__half2*>(Out + (size_t)grow * LDIM + c * 64 + n) = o0;
        *reinterpret_cast<__half2*>(Out + (size_t)(grow + 8) * LDIM + c * 64 + n) = o1;
    }
}

// ---------------- decoder mid: LN(1024) + ReLU -> fp16 (float4 path) ----------------
__global__ __launch_bounds__(256)
void ln_relu_kernel(const float* __restrict__ X, const float* __restrict__ gam,
                    const float* __restrict__ bet, __half* __restrict__ YH)
{
    const int row = blockIdx.x;
    const int tid = threadIdx.x;
    const int lane = tid & 31, wid = tid >> 5;
    __shared__ float red[8], red2[8];

    const float4 v = *reinterpret_cast<const float4*>(X + (size_t)row * LDIM + tid * 4);
    float s  = v.x + v.y + v.z + v.w;
    float s2 = fmaf(v.x, v.x, fmaf(v.y, v.y, fmaf(v.z, v.z, v.w * v.w)));
    #pragma unroll
    for (int o = 16; o; o >>= 1) {
        s  += __shfl_xor_sync(0xffffffffu, s, o);
        s2 += __shfl_xor_sync(0xffffffffu, s2, o);
    }
    if (lane == 0) { red[wid] = s; red2[wid] = s2; }
    __syncthreads();
    if (tid < 32) {
        float a = (tid < 8) ? red[tid] : 0.f;
        float b = (tid < 8) ? red2[tid] : 0.f;
        #pragma unroll
        for (int o = 4; o; o >>= 1) {
            a += __shfl_xor_sync(0xffffffffu, a, o);
            b += __shfl_xor_sync(0xffffffffu, b, o);
        }
        if (tid == 0) { red[0] = a; red2[0] = b; }
    }
    __syncthreads();
    const float mean = red[0] * (1.f / 1024.f);
    const float var  = red2[0] * (1.f / 1024.f) - mean * mean;
    const float rstd = rsqrtf(var + 1e-5f);

    const float4 gv = *reinterpret_cast<const float4*>(gam + tid * 4);
    const float4 bv = *reinterpret_cast<const float4*>(bet + tid * 4);
    __half2 h0 = __floats2half2_rn(fmaxf((v.x - mean) * rstd * gv.x + bv.x, 0.f),
                                   fmaxf((v.y - mean) * rstd * gv.y + bv.y, 0.f));
    __half2 h1 = __floats2half2_rn(fmaxf((v.z - mean) * rstd * gv.z + bv.z, 0.f),
                                   fmaxf((v.w - mean) * rstd * gv.w + bv.w, 0.f));
    uint2 pk = make_uint2(*reinterpret_cast<uint32_t*>(&h0), *reinterpret_cast<uint32_t*>(&h1));
    *reinterpret_cast<uint2*>(YH + (size_t)row * LDIM + tid * 4) = pk;
}

// ---------------- finalize scalars ----------------
__global__ void finalize_kernel(float* __restrict__ out, long long nout)
{
    double kl    = -0.5 * g_kl_sum / ((double)MDIM * (double)LDIM);
    double recon = g_recon_sum / ((double)MDIM * (double)DDIM);
    double dagl  = g_dag_loss;
    double total = recon + 0.3 * kl + 1.0 * dagl;
    long long base = (long long)MDIM * DDIM;
    if (nout >= base + 4) {
        out[base + 0] = (float)total;
        out[base + 1] = (float)kl;
        out[base + 2] = (float)recon;
        out[base + 3] = (float)dagl;
    }
}

// ---------------- launch ----------------
extern "C" void kernel_launch(void* const* d_in, const int* in_sizes, int n_in,
                              void* d_out, int out_size)
{
    (void)in_sizes; (void)n_in;
    const float* x      = (const float*)d_in[0];
    const float* enc_w  = (const float*)d_in[1];
    const float* enc_b  = (const float*)d_in[2];
    const float* enc_g  = (const float*)d_in[3];
    const float* enc_bt = (const float*)d_in[4];
    const float* dag_w  = (const float*)d_in[5];
    const float* cw1    = (const float*)d_in[6];
    const float* cb1    = (const float*)d_in[7];
    const float* cg     = (const float*)d_in[8];
    const float* cbt    = (const float*)d_in[9];
    const float* cw2    = (const float*)d_in[10];
    const float* cb2    = (const float*)d_in[11];
    const float* dec_w1 = (const float*)d_in[12];
    const float* dec_b1 = (const float*)d_in[13];
    const float* dec_g  = (const float*)d_in[14];
    const float* dec_bt = (const float*)d_in[15];
    const float* dec_w2 = (const float*)d_in[16];
    const float* dec_b2 = (const float*)d_in[17];
    float* out = (float*)d_out;

    float *ph, *pdd;
    __half *pxh, *pewh, *pzch, *pzth, *pdh, *pw1h, *pw2h;
    cudaGetSymbolAddress((void**)&ph,   g_h);
    cudaGetSymbolAddress((void**)&pdd,  g_dd);
    cudaGetSymbolAddress((void**)&pxh,  g_xh);
    cudaGetSymbolAddress((void**)&pewh, g_ewh);
    cudaGetSymbolAddress((void**)&pzch, g_zch);
    cudaGetSymbolAddress((void**)&pzth, g_zth);
    cudaGetSymbolAddress((void**)&pdh,  g_dh);
    cudaGetSymbolAddress((void**)&pw1h, g_w1h);
    cudaGetSymbolAddress((void**)&pw2h, g_w2h);

    cudaFuncSetAttribute(mma_gemm_kernel<false>,
                         cudaFuncAttributeMaxDynamicSharedMemorySize, GEMM_SMEM);
    cudaFuncSetAttribute(mma_gemm_kernel<true>,
                         cudaFuncAttributeMaxDynamicSharedMemorySize, GEMM_SMEM);

    // dag + loss-acc init
    dag_kernel<<<1, 256>>>(dag_w);
    // all fp32 -> fp16 conversions in one launch (2-way ILP)
    conv_all_kernel<<<5120, 256>>>(x, pxh, enc_w, pewh, dec_w1, pw1h, dec_w2, pw2h);
    // encoder: h = x @ enc_w^T + enc_b   [16384, 2048]
    mma_gemm_kernel<false><<<dim3(L2DIM / 128, MDIM / 128), 256, GEMM_SMEM>>>(
        pxh, pewh, enc_b, ph, nullptr, L2DIM, DDIM);
    // LN(2L) + KL + causal mix -> fp16 g_zch
    ln_enc_causal_kernel<<<MDIM, 256>>>(enc_g, enc_bt);
    // per-concept transform via mma -> fp16 g_zth
    concept_mma_kernel<<<dim3(MDIM / 128, CN), 256>>>(cw1, cb1, cg, cbt, cw2, cb2,
                                                      pzch, pzth);
    // decoder GEMM 1 -> g_dd
    mma_gemm_kernel<false><<<dim3(LDIM / 128, MDIM / 128), 256, GEMM_SMEM>>>(
        pzth, pw1h, dec_b1, pdd, nullptr, LDIM, LDIM);
    // LN + ReLU -> fp16 g_d
    ln_relu_kernel<<<MDIM, 256>>>(pdd, dec_g, dec_bt, pdh);
    // decoder GEMM 2 -> x_recon (d_out) + fused recon loss
    mma_gemm_kernel<true><<<dim3(DDIM / 128, MDIM / 128), 256, GEMM_SMEM>>>(
        pdh, pw2h, dec_b2, out, x, DDIM, LDIM);
    // scalars
    finalize_kernel<<<1, 1>>>(out, (long long)out_size);
}

// round 16
// speedup vs baseline: 1.0400x; 1.0061x over previous
#include <cuda_runtime.h>
#include <cuda_fp16.h>
#include <math.h>
#include <stdint.h>

// ---------------- problem dims ----------------
#define MDIM 16384          // B*S
#define DDIM 1024           // input dim
#define LDIM 1024           // latent
#define L2DIM 2048          // 2L
#define CN 16               // concepts

// ---------------- scratch (device globals; no allocation) ----------------
__device__ __half g_h [(size_t)MDIM * L2DIM];   // encoder pre-LN output (fp16)
__device__ float g_dd[(size_t)MDIM * LDIM];     // decoder mid pre-LN
__device__ __half g_zch[(size_t)MDIM * LDIM];   // z_causal fp16
__device__ __half g_xh [(size_t)MDIM * DDIM];   // x in fp16
__device__ __half g_zth[(size_t)MDIM * LDIM];   // concept out fp16
__device__ __half g_dh [(size_t)MDIM * LDIM];   // decoder mid fp16
__device__ __half g_ewh[(size_t)L2DIM * DDIM];  // enc_w fp16
__device__ __half g_w1h[(size_t)LDIM * LDIM];   // dec_w1 fp16
__device__ __half g_w2h[(size_t)DDIM * LDIM];   // dec_w2 fp16
__device__ float g_dag[CN * CN];
__device__ double g_kl_sum;
__device__ double g_recon_sum;
__device__ double g_dag_loss;

// ---------------- PTX helpers (baseline ISA only — no tcgen05 on sm_103) ----------
__device__ __forceinline__ uint32_t smem_u32(const void* p) {
    return (uint32_t)__cvta_generic_to_shared(p);
}
__device__ __forceinline__ void cp_async16(uint32_t dst, const void* src) {
    asm volatile("cp.async.cg.shared.global [%0], [%1], 16;" :: "r"(dst), "l"(src));
}
__device__ __forceinline__ void cp_commit() {
    asm volatile("cp.async.commit_group;" ::: "memory");
}
__device__ __forceinline__ void cp_wait1() {
    asm volatile("cp.async.wait_group 1;" ::: "memory");
}
__device__ __forceinline__ void cp_wait0() {
    asm volatile("cp.async.wait_group 0;" ::: "memory");
}
__device__ __forceinline__ void ldm_x4(uint32_t* r, uint32_t addr) {
    asm volatile("ldmatrix.sync.aligned.m8n8.x4.shared.b16 {%0,%1,%2,%3}, [%4];"
                 : "=r"(r[0]), "=r"(r[1]), "=r"(r[2]), "=r"(r[3]) : "r"(addr));
}
__device__ __forceinline__ void mma_fp16(float* c, const uint32_t* a, const uint32_t* b) {
    asm volatile(
        "mma.sync.aligned.m16n8k16.row.col.f32.f16.f16.f32 "
        "{%0,%1,%2,%3}, {%4,%5,%6,%7}, {%8,%9}, {%0,%1,%2,%3};"
        : "+f"(c[0]), "+f"(c[1]), "+f"(c[2]), "+f"(c[3])
        : "r"(a[0]), "r"(a[1]), "r"(a[2]), "r"(a[3]), "r"(b[0]), "r"(b[1]));
}

// ---------------- dag (+ loss-accumulator init) ----------------
// trace(expm(dag)) == C exactly (dag strictly lower triangular -> nilpotent).
__global__ void dag_kernel(const float* __restrict__ dag_w) {
    int tid = threadIdx.x;            // 256 threads
    int i = tid >> 4, j = tid & 15;
    float v = 0.f;
    if (i > j) {
        float x = dag_w[tid];
        v = (x > 20.f) ? x : log1pf(expf(x));
    }
    g_dag[tid] = v;
    __shared__ float sh[8];
    float s = v;
    #pragma unroll
    for (int o = 16; o; o >>= 1) s += __shfl_xor_sync(0xffffffffu, s, o);
    if ((tid & 31) == 0) sh[tid >> 5] = s;
    __syncthreads();
    if (tid == 0) {
        float t = 0.f;
        #pragma unroll
        for (int w = 0; w < 8; w++) t += sh[w];
        g_dag_loss = (double)t + 16.0;
        g_kl_sum = 0.0;
        g_recon_sum = 0.0;
    }
}

// ---------------- fp32 -> fp16 convert, all 4 arrays, 2-way ILP ----------------
// block handles 4096 elems: [0,4096) x | [4096,4608) enc_w | [4608,4864) w1 | [4864,5120) w2
__global__ __launch_bounds__(256)
void conv_all_kernel(const float* __restrict__ X0, __half* __restrict__ H0,
                     const float* __restrict__ X1, __half* __restrict__ H1,
                     const float* __restrict__ X2, __half* __restrict__ H2,
                     const float* __restrict__ X3, __half* __restrict__ H3)
{
    int b = blockIdx.x;
    const float* X; __half* H; int base;
    if (b < 4096)      { X = X0; H = H0; base = b; }
    else if (b < 4608) { X = X1; H = H1; base = b - 4096; }
    else if (b < 4864) { X = X2; H = H2; base = b - 4608; }
    else               { X = X3; H = H3; base = b - 4864; }
    int i0 = base * 4096 + threadIdx.x * 8;
    float4 a0 = *reinterpret_cast<const float4*>(X + i0);
    float4 c0 = *reinterpret_cast<const float4*>(X + i0 + 4);
    float4 a1 = *reinterpret_cast<const float4*>(X + i0 + 2048);
    float4 c1 = *reinterpret_cast<const float4*>(X + i0 + 2052);
    __align__(16) __half h0[8], h1[8];
    h0[0] = __float2half_rn(a0.x); h0[1] = __float2half_rn(a0.y);
    h0[2] = __float2half_rn(a0.z); h0[3] = __float2half_rn(a0.w);
    h0[4] = __float2half_rn(c0.x); h0[5] = __float2half_rn(c0.y);
    h0[6] = __float2half_rn(c0.z); h0[7] = __float2half_rn(c0.w);
    h1[0] = __float2half_rn(a1.x); h1[1] = __float2half_rn(a1.y);
    h1[2] = __float2half_rn(a1.z); h1[3] = __float2half_rn(a1.w);
    h1[4] = __float2half_rn(c1.x); h1[5] = __float2half_rn(c1.y);
    h1[6] = __float2half_rn(c1.z); h1[7] = __float2half_rn(c1.w);
    *reinterpret_cast<uint4*>(H + i0)        = *reinterpret_cast<uint4*>(h0);
    *reinterpret_cast<uint4*>(H + i0 + 2048) = *reinterpret_cast<uint4*>(h1);
}

// ---------------- fp16 mma.sync GEMM: C[M,N] = A[M,K]@W[N,K]^T + bias ----------
// 128x128 tile/CTA, 8 warps (4x2 -> 32x64/warp), KC=32 double-buffered cp.async.
// HALF_OUT: epilogue emits fp16 (half2 stores) instead of fp32.
#define KC 32
#define ROW_B 80                        // bytes/row: 64B data + 16B pad (ldmatrix conflict-free)
#define COMP_BYTES (128 * ROW_B)        // 10240
#define STAGE_BYTES (2 * COMP_BYTES)    // 20480: A, B
#define GEMM_SMEM (2 * STAGE_BYTES)     // 40960

template <bool FUSE_LOSS, bool HALF_OUT>
__global__ __launch_bounds__(256, 2)
void mma_gemm_kernel(const __half* __restrict__ A, const __half* __restrict__ B,
                     const float* __restrict__ bias, void* __restrict__ Cout,
                     const float* __restrict__ Xref, int N, int K)
{
    extern __shared__ char smem_raw[];
    const uint32_t sbase = smem_u32(smem_raw);
    __shared__ float sred[8];

    const int tid  = threadIdx.x;
    const int wid  = tid >> 5;
    const int lane = tid & 31;
    const int bn = blockIdx.x * 128;
    const int bm = blockIdx.y * 128;
    const int warp_m = wid & 3;         // 0..3 -> 32 rows each
    const int warp_n = wid >> 2;        // 0..1 -> 64 cols each

    const __half* srcA = A + (size_t)bm * K;
    const __half* srcB = B + (size_t)bn * K;

    auto load_stage = [&](int c, int s) {
        const uint32_t st = sbase + (uint32_t)s * STAGE_BYTES;
        const int kbase = c * KC;
        #pragma unroll
        for (int h = 0; h < 2; ++h) {           // A: 512 16B-chunks
            int ch = tid + h * 256;
            int row = ch >> 2, part = ch & 3;
            cp_async16(st + row * ROW_B + part * 16,
                       srcA + (size_t)row * K + kbase + part * 8);
        }
        #pragma unroll
        for (int h = 0; h < 2; ++h) {           // B
            int ch = tid + h * 256;
            int row = ch >> 2, part = ch & 3;
            cp_async16(st + COMP_BYTES + row * ROW_B + part * 16,
                       srcB + (size_t)row * K + kbase + part * 8);
        }
        cp_commit();
    };

    // fragment accumulators: [m-tile 0..1][n-tile 0..7][4]
    float acc[2][8][4];
    #pragma unroll
    for (int i = 0; i < 2; i++)
        #pragma unroll
        for (int j = 0; j < 8; j++)
            #pragma unroll
            for (int q = 0; q < 4; q++) acc[i][j][q] = 0.f;

    // per-thread ldmatrix base offsets
    const int a_row = warp_m * 32 + (lane & 15);
    const int a_k   = (lane >> 4) * 8;
    const int b_row = warp_n * 64 + ((lane >> 3) & 2) * 4 + (lane & 7);
    const int b_k   = ((lane >> 3) & 1) * 8;

    const int nch = K / KC;
    load_stage(0, 0);

    for (int c = 0; c < nch; ++c) {
        if (c + 1 < nch) { load_stage(c + 1, (c + 1) & 1); cp_wait1(); }
        else             { cp_wait0(); }
        __syncthreads();

        const uint32_t st = sbase + (uint32_t)(c & 1) * STAGE_BYTES;
        const uint32_t sA = st;
        const uint32_t sB = st + COMP_BYTES;

        #pragma unroll
        for (int ks = 0; ks < 2; ++ks) {
            uint32_t af[2][4];
            #pragma unroll
            for (int mt = 0; mt < 2; ++mt) {
                uint32_t offA = (uint32_t)((a_row + mt * 16) * ROW_B + (a_k + ks * 16) * 2);
                ldm_x4(af[mt], sA + offA);
            }
            #pragma unroll
            for (int np = 0; np < 4; ++np) {
                uint32_t offB = (uint32_t)((b_row + np * 16) * ROW_B + (b_k + ks * 16) * 2);
                uint32_t bf[4];
                ldm_x4(bf, sB + offB);
                #pragma unroll
                for (int mt = 0; mt < 2; ++mt) {
                    mma_fp16(acc[mt][np * 2 + 0], af[mt], bf + 0);
                    mma_fp16(acc[mt][np * 2 + 1], af[mt], bf + 2);
                }
            }
        }
        __syncthreads();
    }

    // ---------------- epilogue: bias add (+ optional recon loss) ----------------
    const int m0 = bm + warp_m * 32;
    const int n0 = bn + warp_n * 64;
    const int rr = lane >> 2;
    const int cq = (lane & 3) * 2;
    float lsum = 0.f;
    #pragma unroll
    for (int mt = 0; mt < 2; ++mt) {
        #pragma unroll
        for (int nt = 0; nt < 8; ++nt) {
            const int m = m0 + mt * 16 + rr;
            const int n = n0 + nt * 8 + cq;
            float2 bv = *reinterpret_cast<const float2*>(bias + n);
            float2 o0 = make_float2(acc[mt][nt][0] + bv.x, acc[mt][nt][1] + bv.y);
            float2 o1 = make_float2(acc[mt][nt][2] + bv.x, acc[mt][nt][3] + bv.y);
            if (FUSE_LOSS) {
                float2 x0 = *reinterpret_cast<const float2*>(Xref + (size_t)m * N + n);
                float2 x1 = *reinterpret_cast<const float2*>(Xref + (size_t)(m + 8) * N + n);
                float d0 = o0.x - x0.x, d1 = o0.y - x0.y;
                float d2 = o1.x - x1.x, d3 = o1.y - x1.y;
                lsum = fmaf(d0, d0, fmaf(d1, d1, fmaf(d2, d2, fmaf(d3, d3, lsum))));
            }
            if (HALF_OUT) {
                __half* Ch = (__half*)Cout;
                *reinterpret_cast<__half2*>(Ch + (size_t)m * N + n)       = __floats2half2_rn(o0.x, o0.y);
                *reinterpret_cast<__half2*>(Ch + (size_t)(m + 8) * N + n) = __floats2half2_rn(o1.x, o1.y);
            } else {
                float* Cf = (float*)Cout;
                *reinterpret_cast<float2*>(Cf + (size_t)m * N + n) = o0;
                *reinterpret_cast<float2*>(Cf + (size_t)(m + 8) * N + n) = o1;
            }
        }
    }
    if (FUSE_LOSS) {
        #pragma unroll
        for (int o = 16; o; o >>= 1) lsum += __shfl_xor_sync(0xffffffffu, lsum, o);
        if (lane == 0) sred[wid] = lsum;
        __syncthreads();
        if (tid == 0) {
            float t = 0.f;
            #pragma unroll
            for (int w = 0; w < 8; w++) t += sred[w];
            atomicAdd(&g_recon_sum, (double)t);
        }
    }
}

// ---------------- causal mix worker: compile-time P => register-resident column ----
// Thread owns column e; computes outputs i = 4P..4P+3 from z[0..4P+3][e] in regs.
template <int P>
__device__ __forceinline__ void causal_cols(const float* __restrict__ zrow,
                                            const float* __restrict__ dag_sh,
                                            __half* __restrict__ outp, int e)
{
    float zr[4 * P + 4];
    #pragma unroll
    for (int j = 0; j < 4 * P + 4; ++j) zr[j] = zrow[(j << 6) + e];   // conflict-free
    #pragma unroll
    for (int qi = 0; qi < 4; ++qi) {
        float a = zr[4 * P + qi];
        #pragma unroll
        for (int j = 0; j < 4 * P + qi; ++j)
            a = fmaf(dag_sh[(4 * P + qi) * 16 + j], zr[j], a);        // dag broadcast
        outp[((4 * P + qi) << 6) + e] = __float2half_rn(a);
    }
}

// ---------------- encoder LN(2L) + KL partial + causal DAG mix, fused --------------
// 256 threads/row; fp16 g_h loads; causal mix register-cached per column (P warp-uniform).
__global__ __launch_bounds__(256)
void ln_enc_causal_kernel(const float* __restrict__ gam, const float* __restrict__ bet)
{
    const int row = blockIdx.x;
    const int tid = threadIdx.x;
    const int lane = tid & 31, wid = tid >> 5;
    __shared__ float zrow[1024];
    __shared__ float dag_sh[256];
    __shared__ float red[8], red2[8], redkl[8];

    dag_sh[tid] = g_dag[tid];

    const __half* h = g_h + (size_t)row * L2DIM;
    const uint2 r0 = *reinterpret_cast<const uint2*>(h + tid * 4);          // mu 4x fp16
    const uint2 r1 = *reinterpret_cast<const uint2*>(h + 1024 + tid * 4);   // logvar
    const float2 m01 = __half22float2(*reinterpret_cast<const __half2*>(&r0.x));
    const float2 m23 = __half22float2(*reinterpret_cast<const __half2*>(&r0.y));
    const float2 l01 = __half22float2(*reinterpret_cast<const __half2*>(&r1.x));
    const float2 l23 = __half22float2(*reinterpret_cast<const __half2*>(&r1.y));
    const float4 v0 = make_float4(m01.x, m01.y, m23.x, m23.y);
    const float4 v1 = make_float4(l01.x, l01.y, l23.x, l23.y);

    float s  = (v0.x + v0.y) + (v0.z + v0.w) + (v1.x + v1.y) + (v1.z + v1.w);
    float s2 = fmaf(v0.x, v0.x, fmaf(v0.y, v0.y, fmaf(v0.z, v0.z, v0.w * v0.w)));
    s2 = fmaf(v1.x, v1.x, fmaf(v1.y, v1.y, fmaf(v1.z, v1.z, fmaf(v1.w, v1.w, s2))));
    #pragma unroll
    for (int o = 16; o; o >>= 1) {
        s  += __shfl_xor_sync(0xffffffffu, s, o);
        s2 += __shfl_xor_sync(0xffffffffu, s2, o);
    }
    if (lane == 0) { red[wid] = s; red2[wid] = s2; }
    __syncthreads();
    if (tid < 32) {
        float a = (tid < 8) ? red[tid] : 0.f;
        float b = (tid < 8) ? red2[tid] : 0.f;
        #pragma unroll
        for (int o = 4; o; o >>= 1) {
            a += __shfl_xor_sync(0xffffffffu, a, o);
            b += __shfl_xor_sync(0xffffffffu, b, o);
        }
        if (tid == 0) { red[0] = a; red2[0] = b; }
    }
    __syncthreads();
    const float mean = red[0] * (1.f / 2048.f);
    const float var  = red2[0] * (1.f / 2048.f) - mean * mean;
    const float rstd = rsqrtf(var + 1e-5f);

    const float4 g0 = *reinterpret_cast<const float4*>(gam + tid * 4);
    const float4 b0 = *reinterpret_cast<const float4*>(bet + tid * 4);
    const float4 g1 = *reinterpret_cast<const float4*>(gam + 1024 + tid * 4);
    const float4 b1 = *reinterpret_cast<const float4*>(bet + 1024 + tid * 4);

    float4 y0;   // mu normalized
    y0.x = (v0.x - mean) * rstd * g0.x + b0.x;
    y0.y = (v0.y - mean) * rstd * g0.y + b0.y;
    y0.z = (v0.z - mean) * rstd * g0.z + b0.z;
    y0.w = (v0.w - mean) * rstd * g0.w + b0.w;
    *reinterpret_cast<float4*>(&zrow[tid * 4]) = y0;

    float4 y1;   // logvar normalized
    y1.x = (v1.x - mean) * rstd * g1.x + b1.x;
    y1.y = (v1.y - mean) * rstd * g1.y + b1.y;
    y1.z = (v1.z - mean) * rstd * g1.z + b1.z;
    y1.w = (v1.w - mean) * rstd * g1.w + b1.w;

    // __expf: MUFU-based; ~1e-6 relative error, negligible inside the 16.8M-term mean
    float kl = -(y0.x * y0.x + y0.y * y0.y + y0.z * y0.z + y0.w * y0.w)
             + 4.f + (y1.x - __expf(y1.x)) + (y1.y - __expf(y1.y))
                   + (y1.z - __expf(y1.z)) + (y1.w - __expf(y1.w));
    #pragma unroll
    for (int o = 16; o; o >>= 1) kl += __shfl_xor_sync(0xffffffffu, kl, o);
    if (lane == 0) redkl[wid] = kl;
    __syncthreads();              // zrow complete + redkl ready
    if (tid == 0) {
        float t = 0.f;
        #pragma unroll
        for (int w = 0; w < 8; w++) t += redkl[w];
        atomicAdd(&g_kl_sum, (double)t);
    }

    // causal: zc[i,e] = z[i,e] + sum_{j<i} dag[i,j]*z[j,e]
    // p = tid>>6 is warp-uniform -> compile-time register arrays, no divergence.
    const int p = tid >> 6, e = tid & 63;
    __half* outp = g_zch + (size_t)row * LDIM;
    if (p == 0)      causal_cols<0>(zrow, dag_sh, outp, e);
    else if (p == 1) causal_cols<1>(zrow, dag_sh, outp, e);
    else if (p == 2) causal_cols<2>(zrow, dag_sh, outp, e);
    else             causal_cols<3>(zrow, dag_sh, outp, e);
}

// ---------------- per-concept via mma: Linear(64) -> LN -> ReLU -> Linear(64) ------
#define CSTRIDE 72      // halves per smem row (144 B -> conflict-free LDSM)

__global__ __launch_bounds__(256)
void concept_mma_kernel(const float* __restrict__ cw1, const float* __restrict__ cb1,
                        const float* __restrict__ cg,  const float* __restrict__ cbt,
                        const float* __restrict__ cw2, const float* __restrict__ cb2,
                        const __half* __restrict__ Z,  __half* __restrict__ Out)
{
    const int c     = blockIdx.y;
    const int rbase = blockIdx.x * 128;
    const int tid   = threadIdx.x;
    const int wid   = tid >> 5;
    const int lane  = tid & 31;

    __shared__ __half w1s[64 * CSTRIDE];
    __shared__ __half w2s[64 * CSTRIDE];
    __shared__ __half zs [128 * CSTRIDE];
    __shared__ float b1s[64], gs[64], bts[64], b2s[64];

    {
        const uint32_t zb = smem_u32(zs);
        #pragma unroll
        for (int h = 0; h < 4; ++h) {
            int i = tid + h * 256;                 // 1024 16B chunks
            int row = i >> 3, part = i & 7;
            cp_async16(zb + row * (CSTRIDE * 2) + part * 16,
                       Z + (size_t)(rbase + row) * LDIM + c * 64 + part * 8);
        }
        cp_commit();
    }
    for (int i = tid; i < 4096; i += 256) {
        int d = i >> 6, e = i & 63;
        w1s[d * CSTRIDE + e] = __float2half_rn(cw1[(size_t)c * 4096 + i]);
        w2s[d * CSTRIDE + e] = __float2half_rn(cw2[(size_t)c * 4096 + i]);
    }
    if (tid < 64) {
        b1s[tid] = cb1[c * 64 + tid];
        gs[tid]  = cg [c * 64 + tid];
        bts[tid] = cbt[c * 64 + tid];
        b2s[tid] = cb2[c * 64 + tid];
    }
    cp_wait0();
    __syncthreads();

    const uint32_t aB = smem_u32(zs)
        + (uint32_t)((wid * 16 + (lane & 15)) * (CSTRIDE * 2) + ((lane >> 4) * 8) * 2);
    uint32_t af[4][4];
    #pragma unroll
    for (int ks = 0; ks < 4; ++ks) ldm_x4(af[ks], aB + ks * 32);

    const int b_row = ((lane >> 3) & 2) * 4 + (lane & 7);
    const int b_k   = ((lane >> 3) & 1) * 8;
    const uint32_t w1B = smem_u32(w1s) + (uint32_t)(b_row * (CSTRIDE * 2) + b_k * 2);
    const uint32_t w2B = smem_u32(w2s) + (uint32_t)(b_row * (CSTRIDE * 2) + b_k * 2);

    float acc[8][4];
    #pragma unroll
    for (int j = 0; j < 8; j++)
        #pragma unroll
        for (int q = 0; q < 4; q++) acc[j][q] = 0.f;

    #pragma unroll
    for (int np = 0; np < 4; ++np) {
        #pragma unroll
        for (int ks = 0; ks < 4; ++ks) {
            uint32_t bf[4];
            ldm_x4(bf, w1B + (uint32_t)(np * 16 * (CSTRIDE * 2) + ks * 32));
            mma_fp16(acc[np * 2 + 0], af[ks], bf + 0);
            mma_fp16(acc[np * 2 + 1], af[ks], bf + 2);
        }
    }

    float s0 = 0.f, q0 = 0.f, s1 = 0.f, q1 = 0.f;
    #pragma unroll
    for (int nt = 0; nt < 8; ++nt) {
        int n = nt * 8 + (lane & 3) * 2;
        float bA = b1s[n], bB = b1s[n + 1];
        acc[nt][0] += bA; acc[nt][1] += bB;
        acc[nt][2] += bA; acc[nt][3] += bB;
        s0 += acc[nt][0] + acc[nt][1];
        q0 = fmaf(acc[nt][0], acc[nt][0], fmaf(acc[nt][1], acc[nt][1], q0));
        s1 += acc[nt][2] + acc[nt][3];
        q1 = fmaf(acc[nt][2], acc[nt][2], fmaf(acc[nt][3], acc[nt][3], q1));
    }
    #pragma unroll
    for (int o = 1; o <= 2; o <<= 1) {
        s0 += __shfl_xor_sync(0xffffffffu, s0, o);
        q0 += __shfl_xor_sync(0xffffffffu, q0, o);
        s1 += __shfl_xor_sync(0xffffffffu, s1, o);
        q1 += __shfl_xor_sync(0xffffffffu, q1, o);
    }
    float m0 = s0 * (1.f / 64.f), v0 = q0 * (1.f / 64.f) - m0 * m0;
    float m1 = s1 * (1.f / 64.f), v1 = q1 * (1.f / 64.f) - m1 * m1;
    float r0 = rsqrtf(v0 + 1e-5f), r1 = rsqrtf(v1 + 1e-5f);

    uint32_t a2[4][4];
    #pragma unroll
    for (int nt = 0; nt < 8; ++nt) {
        int n = nt * 8 + (lane & 3) * 2;
        float gA = gs[n], gB = gs[n + 1], tA = bts[n], tB = bts[n + 1];
        float y00 = fmaxf(fmaf((acc[nt][0] - m0) * r0, gA, tA), 0.f);
        float y01 = fmaxf(fmaf((acc[nt][1] - m0) * r0, gB, tB), 0.f);
        float y10 = fmaxf(fmaf((acc[nt][2] - m1) * r1, gA, tA), 0.f);
        float y11 = fmaxf(fmaf((acc[nt][3] - m1) * r1, gB, tB), 0.f);
        __half2 h0 = __floats2half2_rn(y00, y01);
        __half2 h1 = __floats2half2_rn(y10, y11);
        int kt = nt >> 1;
        if ((nt & 1) == 0) {
            a2[kt][0] = *reinterpret_cast<uint32_t*>(&h0);
            a2[kt][1] = *reinterpret_cast<uint32_t*>(&h1);
        } else {
            a2[kt][2] = *reinterpret_cast<uint32_t*>(&h0);
            a2[kt][3] = *reinterpret_cast<uint32_t*>(&h1);
        }
    }

    float acc2[8][4];
    #pragma unroll
    for (int j = 0; j < 8; j++)
        #pragma unroll
        for (int q = 0; q < 4; q++) acc2[j][q] = 0.f;

    #pragma unroll
    for (int np = 0; np < 4; ++np) {
        #pragma unroll
        for (int ks = 0; ks < 4; ++ks) {
            uint32_t bf[4];
            ldm_x4(bf, w2B + (uint32_t)(np * 16 * (CSTRIDE * 2) + ks * 32));
            mma_fp16(acc2[np * 2 + 0], a2[ks], bf + 0);
            mma_fp16(acc2[np * 2 + 1], a2[ks], bf + 2);
        }
    }

    const int grow = rbase + wid * 16 + (lane >> 2);
    #pragma unroll
    for (int nt = 0; nt < 8; ++nt) {
        int n = nt * 8 + (lane & 3) * 2;
        __half2 o0 = __floats2half2_rn(acc2[nt][0] + b2s[n], acc2[nt][1] + b2s[n + 1]);
        __half2 o1 = __floats2half2_rn(acc2[nt][2] + b2s[n], acc2[nt][3] + b2s[n + 1]);
        *reinterpret_cast<__half2*>(Out + (size_t)grow * LDIM + c * 64 + n) = o0;
        *reinterpret_cast<__half2*>(Out + (size_t)(grow + 8) * LDIM + c * 64 + n) = o1;
    }
}

// ---------------- decoder mid: LN(1024) + ReLU -> fp16 (float4 path) ----------------
__global__ __launch_bounds__(256)
void ln_relu_kernel(const float* __restrict__ X, const float* __restrict__ gam,
                    const float* __restrict__ bet, __half* __restrict__ YH)
{
    const int row = blockIdx.x;
    const int tid = threadIdx.x;
    const int lane = tid & 31, wid = tid >> 5;
    __shared__ float red[8], red2[8];

    const float4 v = *reinterpret_cast<const float4*>(X + (size_t)row * LDIM + tid * 4);
    float s  = v.x + v.y + v.z + v.w;
    float s2 = fmaf(v.x, v.x, fmaf(v.y, v.y, fmaf(v.z, v.z, v.w * v.w)));
    #pragma unroll
    for (int o = 16; o; o >>= 1) {
        s  += __shfl_xor_sync(0xffffffffu, s, o);
        s2 += __shfl_xor_sync(0xffffffffu, s2, o);
    }
    if (lane == 0) { red[wid] = s; red2[wid] = s2; }
    __syncthreads();
    if (tid < 32) {
        float a = (tid < 8) ? red[tid] : 0.f;
        float b = (tid < 8) ? red2[tid] : 0.f;
        #pragma unroll
        for (int o = 4; o; o >>= 1) {
            a += __shfl_xor_sync(0xffffffffu, a, o);
            b += __shfl_xor_sync(0xffffffffu, b, o);
        }
        if (tid == 0) { red[0] = a; red2[0] = b; }
    }
    __syncthreads();
    const float mean = red[0] * (1.f / 1024.f);
    const float var  = red2[0] * (1.f / 1024.f) - mean * mean;
    const float rstd = rsqrtf(var + 1e-5f);

    const float4 gv = *reinterpret_cast<const float4*>(gam + tid * 4);
    const float4 bv = *reinterpret_cast<const float4*>(bet + tid * 4);
    __half2 h0 = __floats2half2_rn(fmaxf((v.x - mean) * rstd * gv.x + bv.x, 0.f),
                                   fmaxf((v.y - mean) * rstd * gv.y + bv.y, 0.f));
    __half2 h1 = __floats2half2_rn(fmaxf((v.z - mean) * rstd * gv.z + bv.z, 0.f),
                                   fmaxf((v.w - mean) * rstd * gv.w + bv.w, 0.f));
    uint2 pk = make_uint2(*reinterpret_cast<uint32_t*>(&h0), *reinterpret_cast<uint32_t*>(&h1));
    *reinterpret_cast<uint2*>(YH + (size_t)row * LDIM + tid * 4) = pk;
}

// ---------------- finalize scalars ----------------
__global__ void finalize_kernel(float* __restrict__ out, long long nout)
{
    double kl    = -0.5 * g_kl_sum / ((double)MDIM * (double)LDIM);
    double recon = g_recon_sum / ((double)MDIM * (double)DDIM);
    double dagl  = g_dag_loss;
    double total = recon + 0.3 * kl + 1.0 * dagl;
    long long base = (long long)MDIM * DDIM;
    if (nout >= base + 4) {
        out[base + 0] = (float)total;
        out[base + 1] = (float)kl;
        out[base + 2] = (float)recon;
        out[base + 3] = (float)dagl;
    }
}

// ---------------- launch ----------------
extern "C" void kernel_launch(void* const* d_in, const int* in_sizes, int n_in,
                              void* d_out, int out_size)
{
    (void)in_sizes; (void)n_in;
    const float* x      = (const float*)d_in[0];
    const float* enc_w  = (const float*)d_in[1];
    const float* enc_b  = (const float*)d_in[2];
    const float* enc_g  = (const float*)d_in[3];
    const float* enc_bt = (const float*)d_in[4];
    const float* dag_w  = (const float*)d_in[5];
    const float* cw1    = (const float*)d_in[6];
    const float* cb1    = (const float*)d_in[7];
    const float* cg     = (const float*)d_in[8];
    const float* cbt    = (const float*)d_in[9];
    const float* cw2    = (const float*)d_in[10];
    const float* cb2    = (const float*)d_in[11];
    const float* dec_w1 = (const float*)d_in[12];
    const float* dec_b1 = (const float*)d_in[13];
    const float* dec_g  = (const float*)d_in[14];
    const float* dec_bt = (const float*)d_in[15];
    const float* dec_w2 = (const float*)d_in[16];
    const float* dec_b2 = (const float*)d_in[17];
    float* out = (float*)d_out;

    float *pdd;
    __half *phh, *pxh, *pewh, *pzch, *pzth, *pdh, *pw1h, *pw2h;
    cudaGetSymbolAddress((void**)&phh,  g_h);
    cudaGetSymbolAddress((void**)&pdd,  g_dd);
    cudaGetSymbolAddress((void**)&pxh,  g_xh);
    cudaGetSymbolAddress((void**)&pewh, g_ewh);
    cudaGetSymbolAddress((void**)&pzch, g_zch);
    cudaGetSymbolAddress((void**)&pzth, g_zth);
    cudaGetSymbolAddress((void**)&pdh,  g_dh);
    cudaGetSymbolAddress((void**)&pw1h, g_w1h);
    cudaGetSymbolAddress((void**)&pw2h, g_w2h);

    cudaFuncSetAttribute(mma_gemm_kernel<false, false>,
                         cudaFuncAttributeMaxDynamicSharedMemorySize, GEMM_SMEM);
    cudaFuncSetAttribute(mma_gemm_kernel<false, true>,
                         cudaFuncAttributeMaxDynamicSharedMemorySize, GEMM_SMEM);
    cudaFuncSetAttribute(mma_gemm_kernel<true, false>,
                         cudaFuncAttributeMaxDynamicSharedMemorySize, GEMM_SMEM);

    // dag + loss-acc init
    dag_kernel<<<1, 256>>>(dag_w);
    // all fp32 -> fp16 conversions in one launch (2-way ILP)
    conv_all_kernel<<<5120, 256>>>(x, pxh, enc_w, pewh, dec_w1, pw1h, dec_w2, pw2h);
    // encoder: h = x @ enc_w^T + enc_b   [16384, 2048] -> fp16
    mma_gemm_kernel<false, true><<<dim3(L2DIM / 128, MDIM / 128), 256, GEMM_SMEM>>>(
        pxh, pewh, enc_b, (void*)phh, nullptr, L2DIM, DDIM);
    // LN(2L) + KL + causal mix -> fp16 g_zch
    ln_enc_causal_kernel<<<MDIM, 256>>>(enc_g, enc_bt);
    // per-concept transform via mma -> fp16 g_zth
    concept_mma_kernel<<<dim3(MDIM / 128, CN), 256>>>(cw1, cb1, cg, cbt, cw2, cb2,
                                                      pzch, pzth);
    // decoder GEMM 1 -> g_dd (fp32)
    mma_gemm_kernel<false, false><<<dim3(LDIM / 128, MDIM / 128), 256, GEMM_SMEM>>>(
        pzth, pw1h, dec_b1, (void*)pdd, nullptr, LDIM, LDIM);
    // LN + ReLU -> fp16 g_d
    ln_relu_kernel<<<MDIM, 256>>>(pdd, dec_g, dec_bt, pdh);
    // decoder GEMM 2 -> x_recon (d_out, fp32) + fused recon loss
    mma_gemm_kernel<true, false><<<dim3(DDIM / 128, MDIM / 128), 256, GEMM_SMEM>>>(
        pdh, pw2h, dec_b2, (void*)out, x, DDIM, LDIM);
    // scalars
    finalize_kernel<<<1, 1>>>(out, (long long)out_size);
}

// round 17
// speedup vs baseline: 1.0430x; 1.0029x over previous
#include <cuda_runtime.h>
#include <cuda_fp16.h>
#include <math.h>
#include <stdint.h>

// ---------------- problem dims ----------------
#define MDIM 16384          // B*S
#define DDIM 1024           // input dim
#define LDIM 1024           // latent
#define L2DIM 2048          // 2L
#define CN 16               // concepts

// ---------------- scratch (device globals; no allocation) ----------------
__device__ __half g_h [(size_t)MDIM * L2DIM];   // encoder pre-LN output (fp16)
__device__ __half g_dd[(size_t)MDIM * LDIM];    // decoder mid pre-LN (fp16)
__device__ __half g_zch[(size_t)MDIM * LDIM];   // z_causal fp16
__device__ __half g_xh [(size_t)MDIM * DDIM];   // x in fp16
__device__ __half g_zth[(size_t)MDIM * LDIM];   // concept out fp16
__device__ __half g_dh [(size_t)MDIM * LDIM];   // decoder mid fp16 (post LN+ReLU)
__device__ __half g_ewh[(size_t)L2DIM * DDIM];  // enc_w fp16
__device__ __half g_w1h[(size_t)LDIM * LDIM];   // dec_w1 fp16
__device__ __half g_w2h[(size_t)DDIM * LDIM];   // dec_w2 fp16
__device__ float g_dag[CN * CN];
__device__ double g_kl_sum;
__device__ double g_recon_sum;
__device__ double g_dag_loss;

// ---------------- PTX helpers (baseline ISA only — no tcgen05 on sm_103) ----------
__device__ __forceinline__ uint32_t smem_u32(const void* p) {
    return (uint32_t)__cvta_generic_to_shared(p);
}
__device__ __forceinline__ void cp_async16(uint32_t dst, const void* src) {
    asm volatile("cp.async.cg.shared.global [%0], [%1], 16;" :: "r"(dst), "l"(src));
}
__device__ __forceinline__ void cp_commit() {
    asm volatile("cp.async.commit_group;" ::: "memory");
}
__device__ __forceinline__ void cp_wait1() {
    asm volatile("cp.async.wait_group 1;" ::: "memory");
}
__device__ __forceinline__ void cp_wait0() {
    asm volatile("cp.async.wait_group 0;" ::: "memory");
}
__device__ __forceinline__ void ldm_x4(uint32_t* r, uint32_t addr) {
    asm volatile("ldmatrix.sync.aligned.m8n8.x4.shared.b16 {%0,%1,%2,%3}, [%4];"
                 : "=r"(r[0]), "=r"(r[1]), "=r"(r[2]), "=r"(r[3]) : "r"(addr));
}
__device__ __forceinline__ void mma_fp16(float* c, const uint32_t* a, const uint32_t* b) {
    asm volatile(
        "mma.sync.aligned.m16n8k16.row.col.f32.f16.f16.f32 "
        "{%0,%1,%2,%3}, {%4,%5,%6,%7}, {%8,%9}, {%0,%1,%2,%3};"
        : "+f"(c[0]), "+f"(c[1]), "+f"(c[2]), "+f"(c[3])
        : "r"(a[0]), "r"(a[1]), "r"(a[2]), "r"(a[3]), "r"(b[0]), "r"(b[1]));
}

// ---------------- dag (+ loss-accumulator init) ----------------
// trace(expm(dag)) == C exactly (dag strictly lower triangular -> nilpotent).
__global__ void dag_kernel(const float* __restrict__ dag_w) {
    int tid = threadIdx.x;            // 256 threads
    int i = tid >> 4, j = tid & 15;
    float v = 0.f;
    if (i > j) {
        float x = dag_w[tid];
        v = (x > 20.f) ? x : log1pf(expf(x));
    }
    g_dag[tid] = v;
    __shared__ float sh[8];
    float s = v;
    #pragma unroll
    for (int o = 16; o; o >>= 1) s += __shfl_xor_sync(0xffffffffu, s, o);
    if ((tid & 31) == 0) sh[tid >> 5] = s;
    __syncthreads();
    if (tid == 0) {
        float t = 0.f;
        #pragma unroll
        for (int w = 0; w < 8; w++) t += sh[w];
        g_dag_loss = (double)t + 16.0;
        g_kl_sum = 0.0;
        g_recon_sum = 0.0;
    }
}

// ---------------- fp32 -> fp16 convert, all 4 arrays, 2-way ILP ----------------
__global__ __launch_bounds__(256)
void conv_all_kernel(const float* __restrict__ X0, __half* __restrict__ H0,
                     const float* __restrict__ X1, __half* __restrict__ H1,
                     const float* __restrict__ X2, __half* __restrict__ H2,
                     const float* __restrict__ X3, __half* __restrict__ H3)
{
    int b = blockIdx.x;
    const float* X; __half* H; int base;
    if (b < 4096)      { X = X0; H = H0; base = b; }
    else if (b < 4608) { X = X1; H = H1; base = b - 4096; }
    else if (b < 4864) { X = X2; H = H2; base = b - 4608; }
    else               { X = X3; H = H3; base = b - 4864; }
    int i0 = base * 4096 + threadIdx.x * 8;
    float4 a0 = *reinterpret_cast<const float4*>(X + i0);
    float4 c0 = *reinterpret_cast<const float4*>(X + i0 + 4);
    float4 a1 = *reinterpret_cast<const float4*>(X + i0 + 2048);
    float4 c1 = *reinterpret_cast<const float4*>(X + i0 + 2052);
    __align__(16) __half h0[8], h1[8];
    h0[0] = __float2half_rn(a0.x); h0[1] = __float2half_rn(a0.y);
    h0[2] = __float2half_rn(a0.z); h0[3] = __float2half_rn(a0.w);
    h0[4] = __float2half_rn(c0.x); h0[5] = __float2half_rn(c0.y);
    h0[6] = __float2half_rn(c0.z); h0[7] = __float2half_rn(c0.w);
    h1[0] = __float2half_rn(a1.x); h1[1] = __float2half_rn(a1.y);
    h1[2] = __float2half_rn(a1.z); h1[3] = __float2half_rn(a1.w);
    h1[4] = __float2half_rn(c1.x); h1[5] = __float2half_rn(c1.y);
    h1[6] = __float2half_rn(c1.z); h1[7] = __float2half_rn(c1.w);
    *reinterpret_cast<uint4*>(H + i0)        = *reinterpret_cast<uint4*>(h0);
    *reinterpret_cast<uint4*>(H + i0 + 2048) = *reinterpret_cast<uint4*>(h1);
}

// ---------------- fp16 mma.sync GEMM: C[M,N] = A[M,K]@W[N,K]^T + bias ----------
#define KC 32
#define ROW_B 80                        // bytes/row: 64B data + 16B pad (ldmatrix conflict-free)
#define COMP_BYTES (128 * ROW_B)        // 10240
#define STAGE_BYTES (2 * COMP_BYTES)    // 20480: A, B
#define GEMM_SMEM (2 * STAGE_BYTES)     // 40960

template <bool FUSE_LOSS, bool HALF_OUT>
__global__ __launch_bounds__(256, 2)
void mma_gemm_kernel(const __half* __restrict__ A, const __half* __restrict__ B,
                     const float* __restrict__ bias, void* __restrict__ Cout,
                     const float* __restrict__ Xref, int N, int K)
{
    extern __shared__ char smem_raw[];
    const uint32_t sbase = smem_u32(smem_raw);
    __shared__ float sred[8];

    const int tid  = threadIdx.x;
    const int wid  = tid >> 5;
    const int lane = tid & 31;
    const int bn = blockIdx.x * 128;
    const int bm = blockIdx.y * 128;
    const int warp_m = wid & 3;
    const int warp_n = wid >> 2;

    const __half* srcA = A + (size_t)bm * K;
    const __half* srcB = B + (size_t)bn * K;

    auto load_stage = [&](int c, int s) {
        const uint32_t st = sbase + (uint32_t)s * STAGE_BYTES;
        const int kbase = c * KC;
        #pragma unroll
        for (int h = 0; h < 2; ++h) {
            int ch = tid + h * 256;
            int row = ch >> 2, part = ch & 3;
            cp_async16(st + row * ROW_B + part * 16,
                       srcA + (size_t)row * K + kbase + part * 8);
        }
        #pragma unroll
        for (int h = 0; h < 2; ++h) {
            int ch = tid + h * 256;
            int row = ch >> 2, part = ch & 3;
            cp_async16(st + COMP_BYTES + row * ROW_B + part * 16,
                       srcB + (size_t)row * K + kbase + part * 8);
        }
        cp_commit();
    };

    float acc[2][8][4];
    #pragma unroll
    for (int i = 0; i < 2; i++)
        #pragma unroll
        for (int j = 0; j < 8; j++)
            #pragma unroll
            for (int q = 0; q < 4; q++) acc[i][j][q] = 0.f;

    const int a_row = warp_m * 32 + (lane & 15);
    const int a_k   = (lane >> 4) * 8;
    const int b_row = warp_n * 64 + ((lane >> 3) & 2) * 4 + (lane & 7);
    const int b_k   = ((lane >> 3) & 1) * 8;

    const int nch = K / KC;
    load_stage(0, 0);

    for (int c = 0; c < nch; ++c) {
        if (c + 1 < nch) { load_stage(c + 1, (c + 1) & 1); cp_wait1(); }
        else             { cp_wait0(); }
        __syncthreads();

        const uint32_t st = sbase + (uint32_t)(c & 1) * STAGE_BYTES;
        const uint32_t sA = st;
        const uint32_t sB = st + COMP_BYTES;

        #pragma unroll
        for (int ks = 0; ks < 2; ++ks) {
            uint32_t af[2][4];
            #pragma unroll
            for (int mt = 0; mt < 2; ++mt) {
                uint32_t offA = (uint32_t)((a_row + mt * 16) * ROW_B + (a_k + ks * 16) * 2);
                ldm_x4(af[mt], sA + offA);
            }
            #pragma unroll
            for (int np = 0; np < 4; ++np) {
                uint32_t offB = (uint32_t)((b_row + np * 16) * ROW_B + (b_k + ks * 16) * 2);
                uint32_t bf[4];
                ldm_x4(bf, sB + offB);
                #pragma unroll
                for (int mt = 0; mt < 2; ++mt) {
                    mma_fp16(acc[mt][np * 2 + 0], af[mt], bf + 0);
                    mma_fp16(acc[mt][np * 2 + 1], af[mt], bf + 2);
                }
            }
        }
        __syncthreads();
    }

    // ---------------- epilogue: bias add (+ optional recon loss) ----------------
    const int m0 = bm + warp_m * 32;
    const int n0 = bn + warp_n * 64;
    const int rr = lane >> 2;
    const int cq = (lane & 3) * 2;
    float lsum = 0.f;
    #pragma unroll
    for (int mt = 0; mt < 2; ++mt) {
        #pragma unroll
        for (int nt = 0; nt < 8; ++nt) {
            const int m = m0 + mt * 16 + rr;
            const int n = n0 + nt * 8 + cq;
            float2 bv = *reinterpret_cast<const float2*>(bias + n);
            float2 o0 = make_float2(acc[mt][nt][0] + bv.x, acc[mt][nt][1] + bv.y);
            float2 o1 = make_float2(acc[mt][nt][2] + bv.x, acc[mt][nt][3] + bv.y);
            if (FUSE_LOSS) {
                float2 x0 = *reinterpret_cast<const float2*>(Xref + (size_t)m * N + n);
                float2 x1 = *reinterpret_cast<const float2*>(Xref + (size_t)(m + 8) * N + n);
                float d0 = o0.x - x0.x, d1 = o0.y - x0.y;
                float d2 = o1.x - x1.x, d3 = o1.y - x1.y;
                lsum = fmaf(d0, d0, fmaf(d1, d1, fmaf(d2, d2, fmaf(d3, d3, lsum))));
            }
            if (HALF_OUT) {
                __half* Ch = (__half*)Cout;
                *reinterpret_cast<__half2*>(Ch + (size_t)m * N + n)       = __floats2half2_rn(o0.x, o0.y);
                *reinterpret_cast<__half2*>(Ch + (size_t)(m + 8) * N + n) = __floats2half2_rn(o1.x, o1.y);
            } else {
                float* Cf = (float*)Cout;
                *reinterpret_cast<float2*>(Cf + (size_t)m * N + n) = o0;
                *reinterpret_cast<float2*>(Cf + (size_t)(m + 8) * N + n) = o1;
            }
        }
    }
    if (FUSE_LOSS) {
        #pragma unroll
        for (int o = 16; o; o >>= 1) lsum += __shfl_xor_sync(0xffffffffu, lsum, o);
        if (lane == 0) sred[wid] = lsum;
        __syncthreads();
        if (tid == 0) {
            float t = 0.f;
            #pragma unroll
            for (int w = 0; w < 8; w++) t += sred[w];
            atomicAdd(&g_recon_sum, (double)t);
        }
    }
}

// ---------------- causal mix worker: compile-time P => register-resident column ----
template <int P>
__device__ __forceinline__ void causal_cols(const float* __restrict__ zrow,
                                            const float* __restrict__ dag_sh,
                                            __half* __restrict__ outp, int e)
{
    float zr[4 * P + 4];
    #pragma unroll
    for (int j = 0; j < 4 * P + 4; ++j) zr[j] = zrow[(j << 6) + e];   // conflict-free
    #pragma unroll
    for (int qi = 0; qi < 4; ++qi) {
        float a = zr[4 * P + qi];
        #pragma unroll
        for (int j = 0; j < 4 * P + qi; ++j)
            a = fmaf(dag_sh[(4 * P + qi) * 16 + j], zr[j], a);        // dag broadcast
        outp[((4 * P + qi) << 6) + e] = __float2half_rn(a);
    }
}

// ---------------- encoder LN(2L) + KL + causal, 2 rows per block (512 thr) --------
// sub-block (256 thr) per row; independent pipelines hide reduction barriers.
__global__ __launch_bounds__(512)
void ln_enc_causal_kernel(const float* __restrict__ gam, const float* __restrict__ bet)
{
    const int sub  = threadIdx.x >> 8;          // 0 or 1 -> row within pair
    const int stid = threadIdx.x & 255;
    const int row  = blockIdx.x * 2 + sub;
    const int lane = stid & 31, wid = stid >> 5;
    __shared__ float zrow[2][1024];
    __shared__ float dag_sh[256];
    __shared__ float red[2][8], red2[2][8], redkl[2][8];

    if (threadIdx.x < 256) dag_sh[threadIdx.x] = g_dag[threadIdx.x];

    const __half* h = g_h + (size_t)row * L2DIM;
    const uint2 r0 = *reinterpret_cast<const uint2*>(h + stid * 4);          // mu
    const uint2 r1 = *reinterpret_cast<const uint2*>(h + 1024 + stid * 4);   // logvar
    const float2 m01 = __half22float2(*reinterpret_cast<const __half2*>(&r0.x));
    const float2 m23 = __half22float2(*reinterpret_cast<const __half2*>(&r0.y));
    const float2 l01 = __half22float2(*reinterpret_cast<const __half2*>(&r1.x));
    const float2 l23 = __half22float2(*reinterpret_cast<const __half2*>(&r1.y));
    const float4 v0 = make_float4(m01.x, m01.y, m23.x, m23.y);
    const float4 v1 = make_float4(l01.x, l01.y, l23.x, l23.y);

    float s  = (v0.x + v0.y) + (v0.z + v0.w) + (v1.x + v1.y) + (v1.z + v1.w);
    float s2 = fmaf(v0.x, v0.x, fmaf(v0.y, v0.y, fmaf(v0.z, v0.z, v0.w * v0.w)));
    s2 = fmaf(v1.x, v1.x, fmaf(v1.y, v1.y, fmaf(v1.z, v1.z, fmaf(v1.w, v1.w, s2))));
    #pragma unroll
    for (int o = 16; o; o >>= 1) {
        s  += __shfl_xor_sync(0xffffffffu, s, o);
        s2 += __shfl_xor_sync(0xffffffffu, s2, o);
    }
    if (lane == 0) { red[sub][wid] = s; red2[sub][wid] = s2; }
    __syncthreads();
    if (stid < 32) {
        float a = (stid < 8) ? red[sub][stid] : 0.f;
        float b = (stid < 8) ? red2[sub][stid] : 0.f;
        #pragma unroll
        for (int o = 4; o; o >>= 1) {
            a += __shfl_xor_sync(0xffffffffu, a, o);
            b += __shfl_xor_sync(0xffffffffu, b, o);
        }
        if (stid == 0) { red[sub][0] = a; red2[sub][0] = b; }
    }
    __syncthreads();
    const float mean = red[sub][0] * (1.f / 2048.f);
    const float var  = red2[sub][0] * (1.f / 2048.f) - mean * mean;
    const float rstd = rsqrtf(var + 1e-5f);

    const float4 g0 = *reinterpret_cast<const float4*>(gam + stid * 4);
    const float4 b0 = *reinterpret_cast<const float4*>(bet + stid * 4);
    const float4 g1 = *reinterpret_cast<const float4*>(gam + 1024 + stid * 4);
    const float4 b1 = *reinterpret_cast<const float4*>(bet + 1024 + stid * 4);

    float4 y0;   // mu normalized
    y0.x = (v0.x - mean) * rstd * g0.x + b0.x;
    y0.y = (v0.y - mean) * rstd * g0.y + b0.y;
    y0.z = (v0.z - mean) * rstd * g0.z + b0.z;
    y0.w = (v0.w - mean) * rstd * g0.w + b0.w;
    *reinterpret_cast<float4*>(&zrow[sub][stid * 4]) = y0;

    float4 y1;   // logvar normalized
    y1.x = (v1.x - mean) * rstd * g1.x + b1.x;
    y1.y = (v1.y - mean) * rstd * g1.y + b1.y;
    y1.z = (v1.z - mean) * rstd * g1.z + b1.z;
    y1.w = (v1.w - mean) * rstd * g1.w + b1.w;

    float kl = -(y0.x * y0.x + y0.y * y0.y + y0.z * y0.z + y0.w * y0.w)
             + 4.f + (y1.x - __expf(y1.x)) + (y1.y - __expf(y1.y))
                   + (y1.z - __expf(y1.z)) + (y1.w - __expf(y1.w));
    #pragma unroll
    for (int o = 16; o; o >>= 1) kl += __shfl_xor_sync(0xffffffffu, kl, o);
    if (lane == 0) redkl[sub][wid] = kl;
    __syncthreads();              // zrow complete + redkl ready
    if (stid == 0) {
        float t = 0.f;
        #pragma unroll
        for (int w = 0; w < 8; w++) t += redkl[sub][w];
        atomicAdd(&g_kl_sum, (double)t);
    }

    // causal: p = stid>>6 is warp-uniform -> compile-time register arrays.
    const int p = stid >> 6, e = stid & 63;
    const float* zr = zrow[sub];
    __half* outp = g_zch + (size_t)row * LDIM;
    if (p == 0)      causal_cols<0>(zr, dag_sh, outp, e);
    else if (p == 1) causal_cols<1>(zr, dag_sh, outp, e);
    else if (p == 2) causal_cols<2>(zr, dag_sh, outp, e);
    else             causal_cols<3>(zr, dag_sh, outp, e);
}

// ---------------- per-concept via mma: Linear(64) -> LN -> ReLU -> Linear(64) ------
#define CSTRIDE 72      // halves per smem row (144 B -> conflict-free LDSM)

__global__ __launch_bounds__(256)
void concept_mma_kernel(const float* __restrict__ cw1, const float* __restrict__ cb1,
                        const float* __restrict__ cg,  const float* __restrict__ cbt,
                        const float* __restrict__ cw2, const float* __restrict__ cb2,
                        const __half* __restrict__ Z,  __half* __restrict__ Out)
{
    const int c     = blockIdx.y;
    const int rbase = blockIdx.x * 128;
    const int tid   = threadIdx.x;
    const int wid   = tid >> 5;
    const int lane  = tid & 31;

    __shared__ __half w1s[64 * CSTRIDE];
    __shared__ __half w2s[64 * CSTRIDE];
    __shared__ __half zs [128 * CSTRIDE];
    __shared__ float b1s[64], gs[64], bts[64], b2s[64];

    {
        const uint32_t zb = smem_u32(zs);
        #pragma unroll
        for (int h = 0; h < 4; ++h) {
            int i = tid + h * 256;                 // 1024 16B chunks
            int row = i >> 3, part = i & 7;
            cp_async16(zb + row * (CSTRIDE * 2) + part * 16,
                       Z + (size_t)(rbase + row) * LDIM + c * 64 + part * 8);
        }
        cp_commit();
    }
    for (int i = tid; i < 4096; i += 256) {
        int d = i >> 6, e = i & 63;
        w1s[d * CSTRIDE + e] = __float2half_rn(cw1[(size_t)c * 4096 + i]);
        w2s[d * CSTRIDE + e] = __float2half_rn(cw2[(size_t)c * 4096 + i]);
    }
    if (tid < 64) {
        b1s[tid] = cb1[c * 64 + tid];
        gs[tid]  = cg [c * 64 + tid];
        bts[tid] = cbt[c * 64 + tid];
        b2s[tid] = cb2[c * 64 + tid];
    }
    cp_wait0();
    __syncthreads();

    const uint32_t aB = smem_u32(zs)
        + (uint32_t)((wid * 16 + (lane & 15)) * (CSTRIDE * 2) + ((lane >> 4) * 8) * 2);
    uint32_t af[4][4];
    #pragma unroll
    for (int ks = 0; ks < 4; ++ks) ldm_x4(af[ks], aB + ks * 32);

    const int b_row = ((lane >> 3) & 2) * 4 + (lane & 7);
    const int b_k   = ((lane >> 3) & 1) * 8;
    const uint32_t w1B = smem_u32(w1s) + (uint32_t)(b_row * (CSTRIDE * 2) + b_k * 2);
    const uint32_t w2B = smem_u32(w2s) + (uint32_t)(b_row * (CSTRIDE * 2) + b_k * 2);

    float acc[8][4];
    #pragma unroll
    for (int j = 0; j < 8; j++)
        #pragma unroll
        for (int q = 0; q < 4; q++) acc[j][q] = 0.f;

    #pragma unroll
    for (int np = 0; np < 4; ++np) {
        #pragma unroll
        for (int ks = 0; ks < 4; ++ks) {
            uint32_t bf[4];
            ldm_x4(bf, w1B + (uint32_t)(np * 16 * (CSTRIDE * 2) + ks * 32));
            mma_fp16(acc[np * 2 + 0], af[ks], bf + 0);
            mma_fp16(acc[np * 2 + 1], af[ks], bf + 2);
        }
    }

    float s0 = 0.f, q0 = 0.f, s1 = 0.f, q1 = 0.f;
    #pragma unroll
    for (int nt = 0; nt < 8; ++nt) {
        int n = nt * 8 + (lane & 3) * 2;
        float bA = b1s[n], bB = b1s[n + 1];
        acc[nt][0] += bA; acc[nt][1] += bB;
        acc[nt][2] += bA; acc[nt][3] += bB;
        s0 += acc[nt][0] + acc[nt][1];
        q0 = fmaf(acc[nt][0], acc[nt][0], fmaf(acc[nt][1], acc[nt][1], q0));
        s1 += acc[nt][2] + acc[nt][3];
        q1 = fmaf(acc[nt][2], acc[nt][2], fmaf(acc[nt][3], acc[nt][3], q1));
    }
    #pragma unroll
    for (int o = 1; o <= 2; o <<= 1) {
        s0 += __shfl_xor_sync(0xffffffffu, s0, o);
        q0 += __shfl_xor_sync(0xffffffffu, q0, o);
        s1 += __shfl_xor_sync(0xffffffffu, s1, o);
        q1 += __shfl_xor_sync(0xffffffffu, q1, o);
    }
    float m0 = s0 * (1.f / 64.f), v0 = q0 * (1.f / 64.f) - m0 * m0;
    float m1 = s1 * (1.f / 64.f), v1 = q1 * (1.f / 64.f) - m1 * m1;
    float r0 = rsqrtf(v0 + 1e-5f), r1 = rsqrtf(v1 + 1e-5f);

    uint32_t a2[4][4];
    #pragma unroll
    for (int nt = 0; nt < 8; ++nt) {
        int n = nt * 8 + (lane & 3) * 2;
        float gA = gs[n], gB = gs[n + 1], tA = bts[n], tB = bts[n + 1];
        float y00 = fmaxf(fmaf((acc[nt][0] - m0) * r0, gA, tA), 0.f);
        float y01 = fmaxf(fmaf((acc[nt][1] - m0) * r0, gB, tB), 0.f);
        float y10 = fmaxf(fmaf((acc[nt][2] - m1) * r1, gA, tA), 0.f);
        float y11 = fmaxf(fmaf((acc[nt][3] - m1) * r1, gB, tB), 0.f);
        __half2 h0 = __floats2half2_rn(y00, y01);
        __half2 h1 = __floats2half2_rn(y10, y11);
        int kt = nt >> 1;
        if ((nt & 1) == 0) {
            a2[kt][0] = *reinterpret_cast<uint32_t*>(&h0);
            a2[kt][1] = *reinterpret_cast<uint32_t*>(&h1);
        } else {
            a2[kt][2] = *reinterpret_cast<uint32_t*>(&h0);
            a2[kt][3] = *reinterpret_cast<uint32_t*>(&h1);
        }
    }

    float acc2[8][4];
    #pragma unroll
    for (int j = 0; j < 8; j++)
        #pragma unroll
        for (int q = 0; q < 4; q++) acc2[j][q] = 0.f;

    #pragma unroll
    for (int np = 0; np < 4; ++np) {
        #pragma unroll
        for (int ks = 0; ks < 4; ++ks) {
            uint32_t bf[4];
            ldm_x4(bf, w2B + (uint32_t)(np * 16 * (CSTRIDE * 2) + ks * 32));
            mma_fp16(acc2[np * 2 + 0], a2[ks], bf + 0);
            mma_fp16(acc2[np * 2 + 1], a2[ks], bf + 2);
        }
    }

    const int grow = rbase + wid * 16 + (lane >> 2);
    #pragma unroll
    for (int nt = 0; nt < 8; ++nt) {
        int n = nt * 8 + (lane & 3) * 2;
        __half2 o0 = __floats2half2_rn(acc2[nt][0] + b2s[n], acc2[nt][1] + b2s[n + 1]);
        __half2 o1 = __floats2half2_rn(acc2[nt][2] + b2s[n], acc2[nt][3] + b2s[n + 1]);
        *reinterpret_cast<__half2*>(Out + (size_t)grow * LDIM + c * 64 + n) = o0;
        *reinterpret_cast<__half2*>(Out + (size_t)(grow + 8) * LDIM + c * 64 + n) = o1;
    }
}

// ---------------- decoder mid: LN(1024) + ReLU, fp16 in -> fp16 out ----------------
__global__ __launch_bounds__(256)
void ln_relu_kernel(const __half* __restrict__ X, const float* __restrict__ gam,
                    const float* __restrict__ bet, __half* __restrict__ YH)
{
    const int row = blockIdx.x;
    const int tid = threadIdx.x;
    const int lane = tid & 31, wid = tid >> 5;
    __shared__ float red[8], red2[8];

    const uint2 rv = *reinterpret_cast<const uint2*>(X + (size_t)row * LDIM + tid * 4);
    const float2 p01 = __half22float2(*reinterpret_cast<const __half2*>(&rv.x));
    const float2 p23 = __half22float2(*reinterpret_cast<const __half2*>(&rv.y));
    const float4 v = make_float4(p01.x, p01.y, p23.x, p23.y);

    float s  = v.x + v.y + v.z + v.w;
    float s2 = fmaf(v.x, v.x, fmaf(v.y, v.y, fmaf(v.z, v.z, v.w * v.w)));
    #pragma unroll
    for (int o = 16; o; o >>= 1) {
        s  += __shfl_xor_sync(0xffffffffu, s, o);
        s2 += __shfl_xor_sync(0xffffffffu, s2, o);
    }
    if (lane == 0) { red[wid] = s; red2[wid] = s2; }
    __syncthreads();
    if (tid < 32) {
        float a = (tid < 8) ? red[tid] : 0.f;
        float b = (tid < 8) ? red2[tid] : 0.f;
        #pragma unroll
        for (int o = 4; o; o >>= 1) {
            a += __shfl_xor_sync(0xffffffffu, a, o);
            b += __shfl_xor_sync(0xffffffffu, b, o);
        }
        if (tid == 0) { red[0] = a; red2[0] = b; }
    }
    __syncthreads();
    const float mean = red[0] * (1.f / 1024.f);
    const float var  = red2[0] * (1.f / 1024.f) - mean * mean;
    const float rstd = rsqrtf(var + 1e-5f);

    const float4 gv = *reinterpret_cast<const float4*>(gam + tid * 4);
    const float4 bv = *reinterpret_cast<const float4*>(bet + tid * 4);
    __half2 h0 = __floats2half2_rn(fmaxf((v.x - mean) * rstd * gv.x + bv.x, 0.f),
                                   fmaxf((v.y - mean) * rstd * gv.y + bv.y, 0.f));
    __half2 h1 = __floats2half2_rn(fmaxf((v.z - mean) * rstd * gv.z + bv.z, 0.f),
                                   fmaxf((v.w - mean) * rstd * gv.w + bv.w, 0.f));
    uint2 pk = make_uint2(*reinterpret_cast<uint32_t*>(&h0), *reinterpret_cast<uint32_t*>(&h1));
    *reinterpret_cast<uint2*>(YH + (size_t)row * LDIM + tid * 4) = pk;
}

// ---------------- finalize scalars ----------------
__global__ void finalize_kernel(float* __restrict__ out, long long nout)
{
    double kl    = -0.5 * g_kl_sum / ((double)MDIM * (double)LDIM);
    double recon = g_recon_sum / ((double)MDIM * (double)DDIM);
    double dagl  = g_dag_loss;
    double total = recon + 0.3 * kl + 1.0 * dagl;
    long long base = (long long)MDIM * DDIM;
    if (nout >= base + 4) {
        out[base + 0] = (float)total;
        out[base + 1] = (float)kl;
        out[base + 2] = (float)recon;
        out[base + 3] = (float)dagl;
    }
}

// ---------------- launch ----------------
extern "C" void kernel_launch(void* const* d_in, const int* in_sizes, int n_in,
                              void* d_out, int out_size)
{
    (void)in_sizes; (void)n_in;
    const float* x      = (const float*)d_in[0];
    const float* enc_w  = (const float*)d_in[1];
    const float* enc_b  = (const float*)d_in[2];
    const float* enc_g  = (const float*)d_in[3];
    const float* enc_bt = (const float*)d_in[4];
    const float* dag_w  = (const float*)d_in[5];
    const float* cw1    = (const float*)d_in[6];
    const float* cb1    = (const float*)d_in[7];
    const float* cg     = (const float*)d_in[8];
    const float* cbt    = (const float*)d_in[9];
    const float* cw2    = (const float*)d_in[10];
    const float* cb2    = (const float*)d_in[11];
    const float* dec_w1 = (const float*)d_in[12];
    const float* dec_b1 = (const float*)d_in[13];
    const float* dec_g  = (const float*)d_in[14];
    const float* dec_bt = (const float*)d_in[15];
    const float* dec_w2 = (const float*)d_in[16];
    const float* dec_b2 = (const float*)d_in[17];
    float* out = (float*)d_out;

    __half *phh, *pdd, *pxh, *pewh, *pzch, *pzth, *pdh, *pw1h, *pw2h;
    cudaGetSymbolAddress((void**)&phh,  g_h);
    cudaGetSymbolAddress((void**)&pdd,  g_dd);
    cudaGetSymbolAddress((void**)&pxh,  g_xh);
    cudaGetSymbolAddress((void**)&pewh, g_ewh);
    cudaGetSymbolAddress((void**)&pzch, g_zch);
    cudaGetSymbolAddress((void**)&pzth, g_zth);
    cudaGetSymbolAddress((void**)&pdh,  g_dh);
    cudaGetSymbolAddress((void**)&pw1h, g_w1h);
    cudaGetSymbolAddress((void**)&pw2h, g_w2h);

    cudaFuncSetAttribute(mma_gemm_kernel<false, false>,
                         cudaFuncAttributeMaxDynamicSharedMemorySize, GEMM_SMEM);
    cudaFuncSetAttribute(mma_gemm_kernel<false, true>,
                         cudaFuncAttributeMaxDynamicSharedMemorySize, GEMM_SMEM);
    cudaFuncSetAttribute(mma_gemm_kernel<true, false>,
                         cudaFuncAttributeMaxDynamicSharedMemorySize, GEMM_SMEM);

    // dag + loss-acc init
    dag_kernel<<<1, 256>>>(dag_w);
    // all fp32 -> fp16 conversions in one launch (2-way ILP)
    conv_all_kernel<<<5120, 256>>>(x, pxh, enc_w, pewh, dec_w1, pw1h, dec_w2, pw2h);
    // encoder: h = x @ enc_w^T + enc_b   [16384, 2048] -> fp16
    mma_gemm_kernel<false, true><<<dim3(L2DIM / 128, MDIM / 128), 256, GEMM_SMEM>>>(
        pxh, pewh, enc_b, (void*)phh, nullptr, L2DIM, DDIM);
    // LN(2L) + KL + causal mix -> fp16 g_zch (2 rows per block)
    ln_enc_causal_kernel<<<MDIM / 2, 512>>>(enc_g, enc_bt);
    // per-concept transform via mma -> fp16 g_zth
    concept_mma_kernel<<<dim3(MDIM / 128, CN), 256>>>(cw1, cb1, cg, cbt, cw2, cb2,
                                                      pzch, pzth);
    // decoder GEMM 1 -> g_dd (fp16)
    mma_gemm_kernel<false, true><<<dim3(LDIM / 128, MDIM / 128), 256, GEMM_SMEM>>>(
        pzth, pw1h, dec_b1, (void*)pdd, nullptr, LDIM, LDIM);
    // LN + ReLU (fp16 in) -> fp16 g_dh
    ln_relu_kernel<<<MDIM, 256>>>(pdd, dec_g, dec_bt, pdh);
    // decoder GEMM 2 -> x_recon (d_out, fp32) + fused recon loss
    mma_gemm_kernel<true, false><<<dim3(DDIM / 128, MDIM / 128), 256, GEMM_SMEM>>>(
        pdh, pw2h, dec_b2, (void*)out, x, DDIM, LDIM);
    // scalars
    finalize_kernel<<<1, 1>>>(out, (long long)out_size);
}